// round 1
// baseline (speedup 1.0000x reference)
#include <cuda_runtime.h>

#define B_ 2
#define S_ 2048
#define D_ 2048
#define H_ 16
#define DH_ 128

// Scratch for projected Q, K, V in [b, h, s, dh] layout (fp32).
__device__ float g_Q[(size_t)B_ * H_ * S_ * DH_];
__device__ float g_K[(size_t)B_ * H_ * S_ * DH_];
__device__ float g_V[(size_t)B_ * H_ * S_ * DH_];

// ---------------------------------------------------------------------------
// Kernel 1: QKV projection GEMM (C[m,n] = sum_k X[m,k] * W[n,k]) with fused
// RoPE (interleaved) on Q/K and 1/sqrt(Dh) folded into Q.
// Tile 128x128x16, 256 threads, 8x8 per-thread microtile.
// blockIdx.z: 0 = Q (rope+scale), 1 = K (rope), 2 = V (plain).
// ---------------------------------------------------------------------------
__global__ __launch_bounds__(256) void proj_rope_kernel(
    const float* __restrict__ x,
    const float* __restrict__ wq,
    const float* __restrict__ wk,
    const float* __restrict__ wv,
    const float* __restrict__ rcos,
    const float* __restrict__ rsin)
{
    __shared__ float As[16][128];   // As[k][m]
    __shared__ float Bs[16][128];   // Bs[k][n]

    const int mode = blockIdx.z;
    const float* __restrict__ w =
        (mode == 0) ? wq : ((mode == 1) ? wk : wv);
    float* __restrict__ outp =
        (mode == 0) ? g_Q : ((mode == 1) ? g_K : g_V);

    const int m0 = blockIdx.y * 128;
    const int n0 = blockIdx.x * 128;
    const int t  = threadIdx.x;
    const int tx = t & 15;
    const int ty = t >> 4;
    const int lr  = t & 127;   // tile row handled by this thread for loads
    const int lcb = t >> 7;    // 0..1

    float acc[8][8];
#pragma unroll
    for (int i = 0; i < 8; i++)
#pragma unroll
        for (int j = 0; j < 8; j++) acc[i][j] = 0.f;

    const float* __restrict__ xrow = x + (size_t)(m0 + lr) * D_;
    const float* __restrict__ wrow = w + (size_t)(n0 + lr) * D_;

    for (int k0 = 0; k0 < D_; k0 += 16) {
        __syncthreads();
#pragma unroll
        for (int rep = 0; rep < 2; rep++) {
            const int c4 = lcb + rep * 2;
            const float4 xa = *(const float4*)(xrow + k0 + c4 * 4);
            As[c4 * 4 + 0][lr] = xa.x;
            As[c4 * 4 + 1][lr] = xa.y;
            As[c4 * 4 + 2][lr] = xa.z;
            As[c4 * 4 + 3][lr] = xa.w;
            const float4 wa = *(const float4*)(wrow + k0 + c4 * 4);
            Bs[c4 * 4 + 0][lr] = wa.x;
            Bs[c4 * 4 + 1][lr] = wa.y;
            Bs[c4 * 4 + 2][lr] = wa.z;
            Bs[c4 * 4 + 3][lr] = wa.w;
        }
        __syncthreads();
#pragma unroll
        for (int kk = 0; kk < 16; kk++) {
            float a[8], bb[8];
            *(float4*)&a[0]  = *(const float4*)&As[kk][ty * 4];
            *(float4*)&a[4]  = *(const float4*)&As[kk][ty * 4 + 64];
            *(float4*)&bb[0] = *(const float4*)&Bs[kk][tx * 4];
            *(float4*)&bb[4] = *(const float4*)&Bs[kk][tx * 4 + 64];
#pragma unroll
            for (int i = 0; i < 8; i++)
#pragma unroll
                for (int j = 0; j < 8; j++)
                    acc[i][j] = fmaf(a[i], bb[j], acc[i][j]);
        }
    }

    const float qscale = 0.08838834764831845f;  // 1/sqrt(128)
#pragma unroll
    for (int i = 0; i < 8; i++) {
        const int mrow = m0 + ty * 4 + ((i < 4) ? i : (60 + i));
        const int b = mrow >> 11;          // / S_
        const int s = mrow & (S_ - 1);     // % S_
#pragma unroll
        for (int j = 0; j < 8; j += 2) {
            const int col = n0 + tx * 4 + ((j < 4) ? j : (60 + j));  // even
            const int h = col >> 7;
            const int d = col & (DH_ - 1);
            const float v0 = acc[i][j];
            const float v1 = acc[i][j + 1];
            float o0, o1;
            if (mode < 2) {
                const float c0  = rcos[s * DH_ + d];
                const float sn0 = rsin[s * DH_ + d];
                const float c1  = rcos[s * DH_ + d + 1];
                const float sn1 = rsin[s * DH_ + d + 1];
                o0 = v0 * c0 - v1 * sn0;
                o1 = v1 * c1 + v0 * sn1;
                if (mode == 0) { o0 *= qscale; o1 *= qscale; }
            } else {
                o0 = v0; o1 = v1;
            }
            const size_t off = ((size_t)(b * H_ + h) * S_ + s) * DH_ + d;
            outp[off]     = o0;
            outp[off + 1] = o1;
        }
    }
}

// ---------------------------------------------------------------------------
// Kernel 2: causal flash attention + final softmax over head dim + transpose.
// Per CTA: one 64-row q tile for one (b,h). 256 threads.
// smem: Qt[128][64], Kt[128][64] (d-major), Vs[64][128], Ps[64][66].
// ---------------------------------------------------------------------------
#define PS_STRIDE 66
#define FA_SMEM_FLOATS (128 * 64 + 128 * 64 + 64 * 128 + 64 * PS_STRIDE)

__global__ __launch_bounds__(256) void fa_kernel(float* __restrict__ out)
{
    extern __shared__ float sm[];
    float* Qt = sm;                       // [d][r] stride 64
    float* Kt = Qt + 128 * 64;            // [d][c] stride 64
    float* Vs = Kt + 128 * 64;            // [c][dv] stride 128
    float* Ps = Vs + 64 * 128;            // [r][c] stride PS_STRIDE

    const int t  = threadIdx.x;
    const int tx = t & 15;
    const int ty = t >> 4;
    const int bh = blockIdx.y;
    const int b  = bh >> 4;
    const int h  = bh & 15;
    // Heavy (large q0) CTAs first: fixes the causal-triangle tail.
    const int q0 = ((int)gridDim.x - 1 - (int)blockIdx.x) * 64;

    const float* __restrict__ Qg = g_Q + ((size_t)bh * S_ + q0) * DH_;
    const float* __restrict__ Kg = g_K + (size_t)bh * S_ * DH_;
    const float* __restrict__ Vg = g_V + (size_t)bh * S_ * DH_;

    // Load Q tile transposed into Qt[d][r]
    {
        const int r  = t & 63;
        const int c0 = t >> 6;  // 0..3
#pragma unroll
        for (int rep = 0; rep < 8; rep++) {
            const int c4 = c0 + rep * 4;
            const float4 v = *(const float4*)(Qg + (size_t)r * DH_ + c4 * 4);
            Qt[(c4 * 4 + 0) * 64 + r] = v.x;
            Qt[(c4 * 4 + 1) * 64 + r] = v.y;
            Qt[(c4 * 4 + 2) * 64 + r] = v.z;
            Qt[(c4 * 4 + 3) * 64 + r] = v.w;
        }
    }

    float m_i[4], l_i[4], o[4][8];
#pragma unroll
    for (int i = 0; i < 4; i++) {
        m_i[i] = -1e30f;
        l_i[i] = 0.f;
#pragma unroll
        for (int jj = 0; jj < 8; jj++) o[i][jj] = 0.f;
    }

    const int nkt = (q0 >> 6) + 1;
    for (int kt = 0; kt < nkt; kt++) {
        const int k0 = kt * 64;
        __syncthreads();  // protect Kt/Vs/Ps from previous iteration's readers

        // K tile transposed into Kt[d][c]
        {
            const int r  = t & 63;
            const int c0 = t >> 6;
#pragma unroll
            for (int rep = 0; rep < 8; rep++) {
                const int c4 = c0 + rep * 4;
                const float4 kv =
                    *(const float4*)(Kg + (size_t)(k0 + r) * DH_ + c4 * 4);
                Kt[(c4 * 4 + 0) * 64 + r] = kv.x;
                Kt[(c4 * 4 + 1) * 64 + r] = kv.y;
                Kt[(c4 * 4 + 2) * 64 + r] = kv.z;
                Kt[(c4 * 4 + 3) * 64 + r] = kv.w;
            }
        }
        // V tile row-major (coalesced load + conflict-free store)
        {
            const int c4v = t & 31;
            const int rv0 = t >> 5;  // 0..7
#pragma unroll
            for (int rep = 0; rep < 8; rep++) {
                const int rv = rv0 + rep * 8;
                const float4 vv =
                    *(const float4*)(Vg + (size_t)(k0 + rv) * DH_ + c4v * 4);
                *(float4*)(Vs + rv * 128 + c4v * 4) = vv;
            }
        }
        __syncthreads();

        // S = Q @ K^T  (4x4 per thread; rows ty*4+i, cols tx*4+j)
        float sc[4][4];
#pragma unroll
        for (int i = 0; i < 4; i++)
#pragma unroll
            for (int j = 0; j < 4; j++) sc[i][j] = 0.f;

#pragma unroll 8
        for (int kk = 0; kk < 128; kk++) {
            const float4 aq = *(const float4*)(Qt + kk * 64 + ty * 4);
            const float4 bk = *(const float4*)(Kt + kk * 64 + tx * 4);
            const float av[4] = {aq.x, aq.y, aq.z, aq.w};
            const float bv[4] = {bk.x, bk.y, bk.z, bk.w};
#pragma unroll
            for (int i = 0; i < 4; i++)
#pragma unroll
                for (int j = 0; j < 4; j++)
                    sc[i][j] = fmaf(av[i], bv[j], sc[i][j]);
        }

        // Causal mask on the diagonal tile (k0 == q0)
        if (kt == nkt - 1) {
#pragma unroll
            for (int i = 0; i < 4; i++)
#pragma unroll
                for (int j = 0; j < 4; j++)
                    if (tx * 4 + j > ty * 4 + i) sc[i][j] = -1e30f;
        }

        // Online softmax update (row groups = 16 lanes sharing ty)
#pragma unroll
        for (int i = 0; i < 4; i++) {
            float tmax = fmaxf(fmaxf(sc[i][0], sc[i][1]),
                               fmaxf(sc[i][2], sc[i][3]));
#pragma unroll
            for (int off = 1; off < 16; off <<= 1)
                tmax = fmaxf(tmax, __shfl_xor_sync(0xffffffffu, tmax, off));
            const float newm = fmaxf(m_i[i], tmax);
            float p[4];
            float tsum = 0.f;
#pragma unroll
            for (int j = 0; j < 4; j++) {
                p[j] = __expf(sc[i][j] - newm);
                tsum += p[j];
            }
#pragma unroll
            for (int off = 1; off < 16; off <<= 1)
                tsum += __shfl_xor_sync(0xffffffffu, tsum, off);
            const float alpha = __expf(m_i[i] - newm);
            l_i[i] = l_i[i] * alpha + tsum;
            m_i[i] = newm;
#pragma unroll
            for (int jj = 0; jj < 8; jj++) o[i][jj] *= alpha;
            float* pr = Ps + (ty * 4 + i) * PS_STRIDE + tx * 4;
            pr[0] = p[0]; pr[1] = p[1]; pr[2] = p[2]; pr[3] = p[3];
        }
        __syncthreads();

        // O += P @ V  (rows ty*4+i, cols tx*8 + jj)
#pragma unroll 4
        for (int c = 0; c < 64; c++) {
            float aa[4];
#pragma unroll
            for (int i = 0; i < 4; i++)
                aa[i] = Ps[(ty * 4 + i) * PS_STRIDE + c];
            const float4 b0 = *(const float4*)(Vs + c * 128 + tx * 8);
            const float4 b1 = *(const float4*)(Vs + c * 128 + tx * 8 + 4);
            const float bb[8] = {b0.x, b0.y, b0.z, b0.w,
                                 b1.x, b1.y, b1.z, b1.w};
#pragma unroll
            for (int i = 0; i < 4; i++)
#pragma unroll
                for (int jj = 0; jj < 8; jj++)
                    o[i][jj] = fmaf(aa[i], bb[jj], o[i][jj]);
        }
    }

    // Normalize, softmax over head dim (128 values/row), transpose-write.
#pragma unroll
    for (int i = 0; i < 4; i++) {
        const float inv = 1.f / l_i[i];
#pragma unroll
        for (int jj = 0; jj < 8; jj++) o[i][jj] *= inv;

        float rmax = o[i][0];
#pragma unroll
        for (int jj = 1; jj < 8; jj++) rmax = fmaxf(rmax, o[i][jj]);
#pragma unroll
        for (int off = 1; off < 16; off <<= 1)
            rmax = fmaxf(rmax, __shfl_xor_sync(0xffffffffu, rmax, off));

        float e[8];
        float ssum = 0.f;
#pragma unroll
        for (int jj = 0; jj < 8; jj++) {
            e[jj] = __expf(o[i][jj] - rmax);
            ssum += e[jj];
        }
#pragma unroll
        for (int off = 1; off < 16; off <<= 1)
            ssum += __shfl_xor_sync(0xffffffffu, ssum, off);
        const float sinv = 1.f / ssum;

        const int srow = q0 + ty * 4 + i;
        float* op = out + ((size_t)b * S_ + srow) * D_ + h * DH_ + tx * 8;
        float4 w0, w1;
        w0.x = e[0] * sinv; w0.y = e[1] * sinv;
        w0.z = e[2] * sinv; w0.w = e[3] * sinv;
        w1.x = e[4] * sinv; w1.y = e[5] * sinv;
        w1.z = e[6] * sinv; w1.w = e[7] * sinv;
        *(float4*)op       = w0;
        *(float4*)(op + 4) = w1;
    }
}

// ---------------------------------------------------------------------------
extern "C" void kernel_launch(void* const* d_in, const int* in_sizes, int n_in,
                              void* d_out, int out_size)
{
    (void)in_sizes; (void)n_in; (void)out_size;
    const float* x  = (const float*)d_in[0];
    const float* wq = (const float*)d_in[1];
    const float* wk = (const float*)d_in[2];
    const float* wv = (const float*)d_in[3];
    const float* rc = (const float*)d_in[4];
    const float* rs = (const float*)d_in[5];
    float* out = (float*)d_out;

    const int fa_smem = FA_SMEM_FLOATS * (int)sizeof(float);  // 115200 B
    cudaFuncSetAttribute(fa_kernel,
                         cudaFuncAttributeMaxDynamicSharedMemorySize, fa_smem);

    dim3 pg(D_ / 128, (B_ * S_) / 128, 3);
    proj_rope_kernel<<<pg, 256>>>(x, wq, wk, wv, rc, rs);

    dim3 fg(S_ / 64, B_ * H_);
    fa_kernel<<<fg, 256, fa_smem>>>(out);
}

// round 5
// speedup vs baseline: 1.6018x; 1.6018x over previous
#include <cuda_runtime.h>
#include <cuda_bf16.h>
#include <cstdint>

#define B_ 2
#define S_ 2048
#define D_ 2048
#define H_ 16
#define DH_ 128

// Scratch for projected Q, K, V in [b, h, s, dh] layout (fp32).
__device__ float g_Q[(size_t)B_ * H_ * S_ * DH_];
__device__ float g_K[(size_t)B_ * H_ * S_ * DH_];
__device__ float g_V[(size_t)B_ * H_ * S_ * DH_];

// ===========================================================================
// Kernel 1: QKV projection via mma.sync bf16 (hi/lo split) + fused RoPE.
// C[m,n] = sum_k X[m,k] W[n,k].  CTA tile 128x256, warp tile 64x64, KC=32,
// double-buffered smem. blockIdx.z: 0 = Q (rope+scale), 1 = K (rope), 2 = V.
// ===========================================================================
#define KC 32
#define NCH (D_ / KC)            // 64
#define AST 40                   // smem row stride (bf16 elems), conflict-free
#define OFF_AH 0
#define OFF_AL (128 * AST)       // 5120
#define OFF_BH (2 * 128 * AST)   // 10240
#define OFF_BL (OFF_BH + 256 * AST)
#define STG_ELEMS (OFF_BL + 256 * AST)   // 30720 elems
#define PROJ_SMEM (2 * STG_ELEMS * 2)    // 122880 bytes

#define MMA16816(d, a, b0v, b1v)                                               \
    asm volatile(                                                              \
        "mma.sync.aligned.m16n8k16.row.col.f32.bf16.bf16.f32 "                 \
        "{%0,%1,%2,%3}, {%4,%5,%6,%7}, {%8,%9}, {%0,%1,%2,%3};"                \
        : "+f"((d)[0]), "+f"((d)[1]), "+f"((d)[2]), "+f"((d)[3])               \
        : "r"((a)[0]), "r"((a)[1]), "r"((a)[2]), "r"((a)[3]),                  \
          "r"(b0v), "r"(b1v))

static __device__ __forceinline__ void split4(float4 v, uint2& hi, uint2& lo) {
    __nv_bfloat16 h0 = __float2bfloat16(v.x);
    __nv_bfloat16 h1 = __float2bfloat16(v.y);
    __nv_bfloat16 h2 = __float2bfloat16(v.z);
    __nv_bfloat16 h3 = __float2bfloat16(v.w);
    __nv_bfloat16 l0 = __float2bfloat16(v.x - __bfloat162float(h0));
    __nv_bfloat16 l1 = __float2bfloat16(v.y - __bfloat162float(h1));
    __nv_bfloat16 l2 = __float2bfloat16(v.z - __bfloat162float(h2));
    __nv_bfloat16 l3 = __float2bfloat16(v.w - __bfloat162float(h3));
    hi.x = ((uint32_t)__bfloat16_as_ushort(h1) << 16) | __bfloat16_as_ushort(h0);
    hi.y = ((uint32_t)__bfloat16_as_ushort(h3) << 16) | __bfloat16_as_ushort(h2);
    lo.x = ((uint32_t)__bfloat16_as_ushort(l1) << 16) | __bfloat16_as_ushort(l0);
    lo.y = ((uint32_t)__bfloat16_as_ushort(l3) << 16) | __bfloat16_as_ushort(l2);
}

__global__ __launch_bounds__(256) void proj_mma_kernel(
    const float* __restrict__ x,
    const float* __restrict__ wq,
    const float* __restrict__ wk,
    const float* __restrict__ wv,
    const float* __restrict__ rcos,
    const float* __restrict__ rsin)
{
    extern __shared__ unsigned short psm[];

    const int mode = blockIdx.z;
    const float* __restrict__ w = (mode == 0) ? wq : ((mode == 1) ? wk : wv);
    float* __restrict__ outp = (mode == 0) ? g_Q : ((mode == 1) ? g_K : g_V);

    const int m0 = blockIdx.y * 128;
    const int n0 = blockIdx.x * 256;
    const int t = threadIdx.x;
    const int lane = t & 31;
    const int wid = t >> 5;
    const int wm = wid & 1;          // 0..1  (m offset 64*wm)
    const int wn = wid >> 1;         // 0..3  (n offset 64*wn)
    const int g = lane >> 2;         // 0..7
    const int tg = lane & 3;         // 0..3

    float acc[4][8][4];
#pragma unroll
    for (int mt = 0; mt < 4; mt++)
#pragma unroll
        for (int nt = 0; nt < 8; nt++)
#pragma unroll
            for (int c = 0; c < 4; c++) acc[mt][nt][c] = 0.f;

    // ---- fill geometry: thread loads float4 at (row, fcol) ----
    const int frow = t >> 3;          // 0..31
    const int fcol = (t & 7) * 4;     // 0..28

    auto fill = [&](int ic, int st) {
        unsigned short* sb = psm + st * STG_ELEMS;
        const int k0 = ic * KC;
#pragma unroll
        for (int p = 0; p < 4; p++) {
            const int row = frow + p * 32;
            float4 v = *(const float4*)(x + (size_t)(m0 + row) * D_ + k0 + fcol);
            uint2 hi, lo; split4(v, hi, lo);
            *(uint2*)(sb + OFF_AH + row * AST + fcol) = hi;
            *(uint2*)(sb + OFF_AL + row * AST + fcol) = lo;
        }
#pragma unroll
        for (int p = 0; p < 8; p++) {
            const int row = frow + p * 32;
            float4 v = *(const float4*)(w + (size_t)(n0 + row) * D_ + k0 + fcol);
            uint2 hi, lo; split4(v, hi, lo);
            *(uint2*)(sb + OFF_BH + row * AST + fcol) = hi;
            *(uint2*)(sb + OFF_BL + row * AST + fcol) = lo;
        }
    };

    auto compute = [&](int st) {
        const unsigned short* sb = psm + st * STG_ELEMS;
#pragma unroll
        for (int ks = 0; ks < 2; ks++) {
            const int kc = ks * 16 + tg * 2;
            uint32_t ah[4][4], al[4][4];
#pragma unroll
            for (int mt = 0; mt < 4; mt++) {
                const int r = wm * 64 + mt * 16 + g;
                const unsigned short* pa = sb + OFF_AH + r * AST + kc;
                ah[mt][0] = *(const uint32_t*)(pa);
                ah[mt][1] = *(const uint32_t*)(pa + 8 * AST);
                ah[mt][2] = *(const uint32_t*)(pa + 8);
                ah[mt][3] = *(const uint32_t*)(pa + 8 * AST + 8);
                const unsigned short* pl = sb + OFF_AL + r * AST + kc;
                al[mt][0] = *(const uint32_t*)(pl);
                al[mt][1] = *(const uint32_t*)(pl + 8 * AST);
                al[mt][2] = *(const uint32_t*)(pl + 8);
                al[mt][3] = *(const uint32_t*)(pl + 8 * AST + 8);
            }
#pragma unroll
            for (int nt = 0; nt < 8; nt++) {
                const int r = wn * 64 + nt * 8 + g;
                const unsigned short* pb = sb + OFF_BH + r * AST + kc;
                const uint32_t bh0 = *(const uint32_t*)(pb);
                const uint32_t bh1 = *(const uint32_t*)(pb + 8);
                const unsigned short* pbl = sb + OFF_BL + r * AST + kc;
                const uint32_t bl0 = *(const uint32_t*)(pbl);
                const uint32_t bl1 = *(const uint32_t*)(pbl + 8);
#pragma unroll
                for (int mt = 0; mt < 4; mt++) {
                    MMA16816(acc[mt][nt], ah[mt], bh0, bh1);
                    MMA16816(acc[mt][nt], ah[mt], bl0, bl1);
                    MMA16816(acc[mt][nt], al[mt], bh0, bh1);
                }
            }
        }
    };

    fill(0, 0);
    __syncthreads();
    for (int ic = 0; ic < NCH; ic++) {
        const int st = ic & 1;
        if (ic + 1 < NCH) fill(ic + 1, st ^ 1);
        compute(st);
        __syncthreads();
    }

    // ---- epilogue: fragment c-pairs are (even d, odd d) -> fused RoPE ----
    const float qscale = 0.08838834764831845f;  // 1/sqrt(128)
#pragma unroll
    for (int mt = 0; mt < 4; mt++) {
#pragma unroll
        for (int half = 0; half < 2; half++) {
            const int m = m0 + wm * 64 + mt * 16 + g + half * 8;
            const int b = m >> 11;
            const int s = m & (S_ - 1);
#pragma unroll
            for (int nt = 0; nt < 8; nt++) {
                const int n = n0 + wn * 64 + nt * 8 + tg * 2;
                const int h = n >> 7;
                const int d = n & (DH_ - 1);
                const float v0 = acc[mt][nt][half * 2];
                const float v1 = acc[mt][nt][half * 2 + 1];
                float o0, o1;
                if (mode < 2) {
                    const float c0  = rcos[s * DH_ + d];
                    const float sn0 = rsin[s * DH_ + d];
                    const float c1  = rcos[s * DH_ + d + 1];
                    const float sn1 = rsin[s * DH_ + d + 1];
                    o0 = v0 * c0 - v1 * sn0;
                    o1 = v1 * c1 + v0 * sn1;
                    if (mode == 0) { o0 *= qscale; o1 *= qscale; }
                } else {
                    o0 = v0; o1 = v1;
                }
                float2 st2; st2.x = o0; st2.y = o1;
                *(float2*)(outp + ((size_t)(b * H_ + h) * S_ + s) * DH_ + d) = st2;
            }
        }
    }
}

// ---------------------------------------------------------------------------
// Kernel 2: causal flash attention + final softmax over head dim + transpose.
// (unchanged from R1 — known good; optimize next round)
// ---------------------------------------------------------------------------
#define PS_STRIDE 66
#define FA_SMEM_FLOATS (128 * 64 + 128 * 64 + 64 * 128 + 64 * PS_STRIDE)

__global__ __launch_bounds__(256) void fa_kernel(float* __restrict__ out)
{
    extern __shared__ float sm[];
    float* Qt = sm;
    float* Kt = Qt + 128 * 64;
    float* Vs = Kt + 128 * 64;
    float* Ps = Vs + 64 * 128;

    const int t  = threadIdx.x;
    const int tx = t & 15;
    const int ty = t >> 4;
    const int bh = blockIdx.y;
    const int b  = bh >> 4;
    const int h  = bh & 15;
    const int q0 = ((int)gridDim.x - 1 - (int)blockIdx.x) * 64;

    const float* __restrict__ Qg = g_Q + ((size_t)bh * S_ + q0) * DH_;
    const float* __restrict__ Kg = g_K + (size_t)bh * S_ * DH_;
    const float* __restrict__ Vg = g_V + (size_t)bh * S_ * DH_;

    {
        const int r  = t & 63;
        const int c0 = t >> 6;
#pragma unroll
        for (int rep = 0; rep < 8; rep++) {
            const int c4 = c0 + rep * 4;
            const float4 v = *(const float4*)(Qg + (size_t)r * DH_ + c4 * 4);
            Qt[(c4 * 4 + 0) * 64 + r] = v.x;
            Qt[(c4 * 4 + 1) * 64 + r] = v.y;
            Qt[(c4 * 4 + 2) * 64 + r] = v.z;
            Qt[(c4 * 4 + 3) * 64 + r] = v.w;
        }
    }

    float m_i[4], l_i[4], o[4][8];
#pragma unroll
    for (int i = 0; i < 4; i++) {
        m_i[i] = -1e30f;
        l_i[i] = 0.f;
#pragma unroll
        for (int jj = 0; jj < 8; jj++) o[i][jj] = 0.f;
    }

    const int nkt = (q0 >> 6) + 1;
    for (int kt = 0; kt < nkt; kt++) {
        const int k0 = kt * 64;
        __syncthreads();

        {
            const int r  = t & 63;
            const int c0 = t >> 6;
#pragma unroll
            for (int rep = 0; rep < 8; rep++) {
                const int c4 = c0 + rep * 4;
                const float4 kv =
                    *(const float4*)(Kg + (size_t)(k0 + r) * DH_ + c4 * 4);
                Kt[(c4 * 4 + 0) * 64 + r] = kv.x;
                Kt[(c4 * 4 + 1) * 64 + r] = kv.y;
                Kt[(c4 * 4 + 2) * 64 + r] = kv.z;
                Kt[(c4 * 4 + 3) * 64 + r] = kv.w;
            }
        }
        {
            const int c4v = t & 31;
            const int rv0 = t >> 5;
#pragma unroll
            for (int rep = 0; rep < 8; rep++) {
                const int rv = rv0 + rep * 8;
                const float4 vv =
                    *(const float4*)(Vg + (size_t)(k0 + rv) * DH_ + c4v * 4);
                *(float4*)(Vs + rv * 128 + c4v * 4) = vv;
            }
        }
        __syncthreads();

        float sc[4][4];
#pragma unroll
        for (int i = 0; i < 4; i++)
#pragma unroll
            for (int j = 0; j < 4; j++) sc[i][j] = 0.f;

#pragma unroll 8
        for (int kk = 0; kk < 128; kk++) {
            const float4 aq = *(const float4*)(Qt + kk * 64 + ty * 4);
            const float4 bk = *(const float4*)(Kt + kk * 64 + tx * 4);
            const float av[4] = {aq.x, aq.y, aq.z, aq.w};
            const float bv[4] = {bk.x, bk.y, bk.z, bk.w};
#pragma unroll
            for (int i = 0; i < 4; i++)
#pragma unroll
                for (int j = 0; j < 4; j++)
                    sc[i][j] = fmaf(av[i], bv[j], sc[i][j]);
        }

        if (kt == nkt - 1) {
#pragma unroll
            for (int i = 0; i < 4; i++)
#pragma unroll
                for (int j = 0; j < 4; j++)
                    if (tx * 4 + j > ty * 4 + i) sc[i][j] = -1e30f;
        }

#pragma unroll
        for (int i = 0; i < 4; i++) {
            float tmax = fmaxf(fmaxf(sc[i][0], sc[i][1]),
                               fmaxf(sc[i][2], sc[i][3]));
#pragma unroll
            for (int off = 1; off < 16; off <<= 1)
                tmax = fmaxf(tmax, __shfl_xor_sync(0xffffffffu, tmax, off));
            const float newm = fmaxf(m_i[i], tmax);
            float p[4];
            float tsum = 0.f;
#pragma unroll
            for (int j = 0; j < 4; j++) {
                p[j] = __expf(sc[i][j] - newm);
                tsum += p[j];
            }
#pragma unroll
            for (int off = 1; off < 16; off <<= 1)
                tsum += __shfl_xor_sync(0xffffffffu, tsum, off);
            const float alpha = __expf(m_i[i] - newm);
            l_i[i] = l_i[i] * alpha + tsum;
            m_i[i] = newm;
#pragma unroll
            for (int jj = 0; jj < 8; jj++) o[i][jj] *= alpha;
            float* pr = Ps + (ty * 4 + i) * PS_STRIDE + tx * 4;
            pr[0] = p[0]; pr[1] = p[1]; pr[2] = p[2]; pr[3] = p[3];
        }
        __syncthreads();

#pragma unroll 4
        for (int c = 0; c < 64; c++) {
            float aa[4];
#pragma unroll
            for (int i = 0; i < 4; i++)
                aa[i] = Ps[(ty * 4 + i) * PS_STRIDE + c];
            const float4 b0 = *(const float4*)(Vs + c * 128 + tx * 8);
            const float4 b1 = *(const float4*)(Vs + c * 128 + tx * 8 + 4);
            const float bb[8] = {b0.x, b0.y, b0.z, b0.w,
                                 b1.x, b1.y, b1.z, b1.w};
#pragma unroll
            for (int i = 0; i < 4; i++)
#pragma unroll
                for (int jj = 0; jj < 8; jj++)
                    o[i][jj] = fmaf(aa[i], bb[jj], o[i][jj]);
        }
    }

#pragma unroll
    for (int i = 0; i < 4; i++) {
        const float inv = 1.f / l_i[i];
#pragma unroll
        for (int jj = 0; jj < 8; jj++) o[i][jj] *= inv;

        float rmax = o[i][0];
#pragma unroll
        for (int jj = 1; jj < 8; jj++) rmax = fmaxf(rmax, o[i][jj]);
#pragma unroll
        for (int off = 1; off < 16; off <<= 1)
            rmax = fmaxf(rmax, __shfl_xor_sync(0xffffffffu, rmax, off));

        float e[8];
        float ssum = 0.f;
#pragma unroll
        for (int jj = 0; jj < 8; jj++) {
            e[jj] = __expf(o[i][jj] - rmax);
            ssum += e[jj];
        }
#pragma unroll
        for (int off = 1; off < 16; off <<= 1)
            ssum += __shfl_xor_sync(0xffffffffu, ssum, off);
        const float sinv = 1.f / ssum;

        const int srow = q0 + ty * 4 + i;
        float* op = out + ((size_t)b * S_ + srow) * D_ + h * DH_ + tx * 8;
        float4 w0, w1;
        w0.x = e[0] * sinv; w0.y = e[1] * sinv;
        w0.z = e[2] * sinv; w0.w = e[3] * sinv;
        w1.x = e[4] * sinv; w1.y = e[5] * sinv;
        w1.z = e[6] * sinv; w1.w = e[7] * sinv;
        *(float4*)op       = w0;
        *(float4*)(op + 4) = w1;
    }
}

// ---------------------------------------------------------------------------
extern "C" void kernel_launch(void* const* d_in, const int* in_sizes, int n_in,
                              void* d_out, int out_size)
{
    (void)in_sizes; (void)n_in; (void)out_size;
    const float* x  = (const float*)d_in[0];
    const float* wq = (const float*)d_in[1];
    const float* wk = (const float*)d_in[2];
    const float* wv = (const float*)d_in[3];
    const float* rc = (const float*)d_in[4];
    const float* rs = (const float*)d_in[5];
    float* out = (float*)d_out;

    cudaFuncSetAttribute(proj_mma_kernel,
                         cudaFuncAttributeMaxDynamicSharedMemorySize, PROJ_SMEM);
    const int fa_smem = FA_SMEM_FLOATS * (int)sizeof(float);
    cudaFuncSetAttribute(fa_kernel,
                         cudaFuncAttributeMaxDynamicSharedMemorySize, fa_smem);

    dim3 pg(D_ / 256, (B_ * S_) / 128, 3);
    proj_mma_kernel<<<pg, 256, PROJ_SMEM>>>(x, wq, wk, wv, rc, rs);

    dim3 fg(S_ / 64, B_ * H_);
    fa_kernel<<<fg, 256, fa_smem>>>(out);
}

// round 9
// speedup vs baseline: 2.3737x; 1.4819x over previous
#include <cuda_runtime.h>
#include <cuda_bf16.h>
#include <cstdint>

#define B_ 2
#define S_ 2048
#define D_ 2048
#define H_ 16
#define DH_ 128

// Scratch for projected Q, K, V in [b, h, s, dh] layout (fp32).
__device__ float g_Q[(size_t)B_ * H_ * S_ * DH_];
__device__ float g_K[(size_t)B_ * H_ * S_ * DH_];
__device__ float g_V[(size_t)B_ * H_ * S_ * DH_];

#define MMA16816(d, a, b0v, b1v)                                               \
    asm volatile(                                                              \
        "mma.sync.aligned.m16n8k16.row.col.f32.bf16.bf16.f32 "                 \
        "{%0,%1,%2,%3}, {%4,%5,%6,%7}, {%8,%9}, {%0,%1,%2,%3};"                \
        : "+f"((d)[0]), "+f"((d)[1]), "+f"((d)[2]), "+f"((d)[3])               \
        : "r"((a)[0]), "r"((a)[1]), "r"((a)[2]), "r"((a)[3]),                  \
          "r"(b0v), "r"(b1v))

static __device__ __forceinline__ void split4(float4 v, uint2& hi, uint2& lo) {
    __nv_bfloat16 h0 = __float2bfloat16(v.x);
    __nv_bfloat16 h1 = __float2bfloat16(v.y);
    __nv_bfloat16 h2 = __float2bfloat16(v.z);
    __nv_bfloat16 h3 = __float2bfloat16(v.w);
    __nv_bfloat16 l0 = __float2bfloat16(v.x - __bfloat162float(h0));
    __nv_bfloat16 l1 = __float2bfloat16(v.y - __bfloat162float(h1));
    __nv_bfloat16 l2 = __float2bfloat16(v.z - __bfloat162float(h2));
    __nv_bfloat16 l3 = __float2bfloat16(v.w - __bfloat162float(h3));
    hi.x = ((uint32_t)__bfloat16_as_ushort(h1) << 16) | __bfloat16_as_ushort(h0);
    hi.y = ((uint32_t)__bfloat16_as_ushort(h3) << 16) | __bfloat16_as_ushort(h2);
    lo.x = ((uint32_t)__bfloat16_as_ushort(l1) << 16) | __bfloat16_as_ushort(l0);
    lo.y = ((uint32_t)__bfloat16_as_ushort(l3) << 16) | __bfloat16_as_ushort(l2);
}
static __device__ __forceinline__ void split2(float x, float y,
                                              uint32_t& hi, uint32_t& lo) {
    __nv_bfloat16 hx = __float2bfloat16(x);
    __nv_bfloat16 hy = __float2bfloat16(y);
    __nv_bfloat16 lx = __float2bfloat16(x - __bfloat162float(hx));
    __nv_bfloat16 ly = __float2bfloat16(y - __bfloat162float(hy));
    hi = ((uint32_t)__bfloat16_as_ushort(hy) << 16) | __bfloat16_as_ushort(hx);
    lo = ((uint32_t)__bfloat16_as_ushort(ly) << 16) | __bfloat16_as_ushort(lx);
}

// ===========================================================================
// Kernel 1: QKV projection via mma.sync bf16 (hi/lo split) + fused RoPE.
// (unchanged — known good)
// ===========================================================================
#define KC 32
#define NCH (D_ / KC)            // 64
#define AST 40
#define OFF_AH 0
#define OFF_AL (128 * AST)
#define OFF_BH (2 * 128 * AST)
#define OFF_BL (OFF_BH + 256 * AST)
#define STG_ELEMS (OFF_BL + 256 * AST)
#define PROJ_SMEM (2 * STG_ELEMS * 2)

__global__ __launch_bounds__(256) void proj_mma_kernel(
    const float* __restrict__ x,
    const float* __restrict__ wq,
    const float* __restrict__ wk,
    const float* __restrict__ wv,
    const float* __restrict__ rcos,
    const float* __restrict__ rsin)
{
    extern __shared__ unsigned short psm[];

    const int mode = blockIdx.z;
    const float* __restrict__ w = (mode == 0) ? wq : ((mode == 1) ? wk : wv);
    float* __restrict__ outp = (mode == 0) ? g_Q : ((mode == 1) ? g_K : g_V);

    const int m0 = blockIdx.y * 128;
    const int n0 = blockIdx.x * 256;
    const int t = threadIdx.x;
    const int lane = t & 31;
    const int wid = t >> 5;
    const int wm = wid & 1;
    const int wn = wid >> 1;
    const int g = lane >> 2;
    const int tg = lane & 3;

    float acc[4][8][4];
#pragma unroll
    for (int mt = 0; mt < 4; mt++)
#pragma unroll
        for (int nt = 0; nt < 8; nt++)
#pragma unroll
            for (int c = 0; c < 4; c++) acc[mt][nt][c] = 0.f;

    const int frow = t >> 3;
    const int fcol = (t & 7) * 4;

    auto fill = [&](int ic, int st) {
        unsigned short* sb = psm + st * STG_ELEMS;
        const int k0 = ic * KC;
#pragma unroll
        for (int p = 0; p < 4; p++) {
            const int row = frow + p * 32;
            float4 v = *(const float4*)(x + (size_t)(m0 + row) * D_ + k0 + fcol);
            uint2 hi, lo; split4(v, hi, lo);
            *(uint2*)(sb + OFF_AH + row * AST + fcol) = hi;
            *(uint2*)(sb + OFF_AL + row * AST + fcol) = lo;
        }
#pragma unroll
        for (int p = 0; p < 8; p++) {
            const int row = frow + p * 32;
            float4 v = *(const float4*)(w + (size_t)(n0 + row) * D_ + k0 + fcol);
            uint2 hi, lo; split4(v, hi, lo);
            *(uint2*)(sb + OFF_BH + row * AST + fcol) = hi;
            *(uint2*)(sb + OFF_BL + row * AST + fcol) = lo;
        }
    };

    auto compute = [&](int st) {
        const unsigned short* sb = psm + st * STG_ELEMS;
#pragma unroll
        for (int ks = 0; ks < 2; ks++) {
            const int kc = ks * 16 + tg * 2;
            uint32_t ah[4][4], al[4][4];
#pragma unroll
            for (int mt = 0; mt < 4; mt++) {
                const int r = wm * 64 + mt * 16 + g;
                const unsigned short* pa = sb + OFF_AH + r * AST + kc;
                ah[mt][0] = *(const uint32_t*)(pa);
                ah[mt][1] = *(const uint32_t*)(pa + 8 * AST);
                ah[mt][2] = *(const uint32_t*)(pa + 8);
                ah[mt][3] = *(const uint32_t*)(pa + 8 * AST + 8);
                const unsigned short* pl = sb + OFF_AL + r * AST + kc;
                al[mt][0] = *(const uint32_t*)(pl);
                al[mt][1] = *(const uint32_t*)(pl + 8 * AST);
                al[mt][2] = *(const uint32_t*)(pl + 8);
                al[mt][3] = *(const uint32_t*)(pl + 8 * AST + 8);
            }
#pragma unroll
            for (int nt = 0; nt < 8; nt++) {
                const int r = wn * 64 + nt * 8 + g;
                const unsigned short* pb = sb + OFF_BH + r * AST + kc;
                const uint32_t bh0 = *(const uint32_t*)(pb);
                const uint32_t bh1 = *(const uint32_t*)(pb + 8);
                const unsigned short* pbl = sb + OFF_BL + r * AST + kc;
                const uint32_t bl0 = *(const uint32_t*)(pbl);
                const uint32_t bl1 = *(const uint32_t*)(pbl + 8);
#pragma unroll
                for (int mt = 0; mt < 4; mt++) {
                    MMA16816(acc[mt][nt], ah[mt], bh0, bh1);
                    MMA16816(acc[mt][nt], ah[mt], bl0, bl1);
                    MMA16816(acc[mt][nt], al[mt], bh0, bh1);
                }
            }
        }
    };

    fill(0, 0);
    __syncthreads();
    for (int ic = 0; ic < NCH; ic++) {
        const int st = ic & 1;
        if (ic + 1 < NCH) fill(ic + 1, st ^ 1);
        compute(st);
        __syncthreads();
    }

    const float qscale = 0.08838834764831845f;
#pragma unroll
    for (int mt = 0; mt < 4; mt++) {
#pragma unroll
        for (int half = 0; half < 2; half++) {
            const int m = m0 + wm * 64 + mt * 16 + g + half * 8;
            const int b = m >> 11;
            const int s = m & (S_ - 1);
#pragma unroll
            for (int nt = 0; nt < 8; nt++) {
                const int n = n0 + wn * 64 + nt * 8 + tg * 2;
                const int h = n >> 7;
                const int d = n & (DH_ - 1);
                const float v0 = acc[mt][nt][half * 2];
                const float v1 = acc[mt][nt][half * 2 + 1];
                float o0, o1;
                if (mode < 2) {
                    const float c0  = rcos[s * DH_ + d];
                    const float sn0 = rsin[s * DH_ + d];
                    const float c1  = rcos[s * DH_ + d + 1];
                    const float sn1 = rsin[s * DH_ + d + 1];
                    o0 = v0 * c0 - v1 * sn0;
                    o1 = v1 * c1 + v0 * sn1;
                    if (mode == 0) { o0 *= qscale; o1 *= qscale; }
                } else {
                    o0 = v0; o1 = v1;
                }
                float2 st2; st2.x = o0; st2.y = o1;
                *(float2*)(outp + ((size_t)(b * H_ + h) * S_ + s) * DH_ + d) = st2;
            }
        }
    }
}

// ===========================================================================
// Kernel 2: flash attention via mma.sync bf16 hi/lo + fused second softmax.
// CTA: 128 thr / 4 warps. BQ=64 (warp = 16 q rows), BK=64.
// R8 bug fixed: K-tile loader now covers all 64x128 elements.
// ===========================================================================
#define KST 136              // K tile row stride (bf16 elems)
#define VST 72               // Vt row stride
#define FA_KH 0
#define FA_KL (64 * KST)
#define FA_VH (2 * 64 * KST)
#define FA_VL (FA_VH + 128 * VST)
#define FA_ELEMS (FA_VL + 128 * VST)
#define FA_SMEM_B (FA_ELEMS * 2)   // 71680 bytes

__global__ __launch_bounds__(128, 2) void fa_mma_kernel(float* __restrict__ out)
{
    extern __shared__ unsigned short fsm[];
    unsigned short* KH = fsm + FA_KH;
    unsigned short* KL = fsm + FA_KL;
    unsigned short* VH = fsm + FA_VH;
    unsigned short* VL = fsm + FA_VL;

    const int t = threadIdx.x;
    const int lane = t & 31;
    const int wid = t >> 5;
    const int g = lane >> 2;
    const int tg = lane & 3;
    const int bh = blockIdx.y;
    const int b = bh >> 4;
    const int h = bh & 15;
    const int q0 = ((int)gridDim.x - 1 - (int)blockIdx.x) * 64;
    const int qrow0 = q0 + wid * 16;

    const float* __restrict__ Qg = g_Q + ((size_t)bh * S_ + qrow0) * DH_;
    const float* __restrict__ Kg = g_K + (size_t)bh * S_ * DH_;
    const float* __restrict__ Vg = g_V + (size_t)bh * S_ * DH_;

    // Q fragments (hi/lo), register resident.
    uint32_t qh[8][4], ql[8][4];
#pragma unroll
    for (int ks = 0; ks < 8; ks++) {
        const int kc = ks * 16 + tg * 2;
        float2 v0 = *(const float2*)(Qg + (size_t)g * DH_ + kc);
        float2 v1 = *(const float2*)(Qg + (size_t)(g + 8) * DH_ + kc);
        float2 v2 = *(const float2*)(Qg + (size_t)g * DH_ + kc + 8);
        float2 v3 = *(const float2*)(Qg + (size_t)(g + 8) * DH_ + kc + 8);
        split2(v0.x, v0.y, qh[ks][0], ql[ks][0]);
        split2(v1.x, v1.y, qh[ks][1], ql[ks][1]);
        split2(v2.x, v2.y, qh[ks][2], ql[ks][2]);
        split2(v3.x, v3.y, qh[ks][3], ql[ks][3]);
    }

    float m0 = -1e30f, m1 = -1e30f, l0 = 0.f, l1 = 0.f;
    float o[16][4];
#pragma unroll
    for (int nt = 0; nt < 16; nt++)
#pragma unroll
        for (int c = 0; c < 4; c++) o[nt][c] = 0.f;

    const int nkt = (q0 >> 6) + 1;
    for (int kt = 0; kt < nkt; kt++) {
        const int k0 = kt * 64;
        __syncthreads();

        // K tile: rows = seq (n), cols = d (k). FIXED: full 64x128 coverage.
        {
            const int fr = t >> 5;          // 0..3
            const int fc = (t & 31) * 4;    // 0..124
#pragma unroll
            for (int p = 0; p < 16; p++) {
                const int row = fr + p * 4;
                float4 v = *(const float4*)(Kg + (size_t)(k0 + row) * DH_ + fc);
                uint2 hi, lo; split4(v, hi, lo);
                *(uint2*)(KH + row * KST + fc) = hi;
                *(uint2*)(KL + row * KST + fc) = lo;
            }
        }
        // V tile transposed: Vt[d][s]
        {
            const int sv = t & 63;
            const int cb = t >> 6;
#pragma unroll
            for (int it = 0; it < 16; it++) {
                const int d0 = (cb + it * 2) * 4;
                float4 v = *(const float4*)(Vg + (size_t)(k0 + sv) * DH_ + d0);
                float vv[4] = {v.x, v.y, v.z, v.w};
#pragma unroll
                for (int i = 0; i < 4; i++) {
                    __nv_bfloat16 hb = __float2bfloat16(vv[i]);
                    __nv_bfloat16 lb =
                        __float2bfloat16(vv[i] - __bfloat162float(hb));
                    VH[(d0 + i) * VST + sv] = __bfloat16_as_ushort(hb);
                    VL[(d0 + i) * VST + sv] = __bfloat16_as_ushort(lb);
                }
            }
        }
        __syncthreads();

        // S = Q K^T (16 x 64 per warp), hi/lo compensated
        float sc[8][4];
#pragma unroll
        for (int nt = 0; nt < 8; nt++)
#pragma unroll
            for (int c = 0; c < 4; c++) sc[nt][c] = 0.f;

#pragma unroll
        for (int nt = 0; nt < 8; nt++) {
            const int r = nt * 8 + g;
#pragma unroll
            for (int ks = 0; ks < 8; ks++) {
                const int kc = ks * 16 + tg * 2;
                const unsigned short* pb = KH + r * KST + kc;
                const uint32_t bh0 = *(const uint32_t*)(pb);
                const uint32_t bh1 = *(const uint32_t*)(pb + 8);
                const unsigned short* pl = KL + r * KST + kc;
                const uint32_t bl0 = *(const uint32_t*)(pl);
                const uint32_t bl1 = *(const uint32_t*)(pl + 8);
                MMA16816(sc[nt], qh[ks], bh0, bh1);
                MMA16816(sc[nt], qh[ks], bl0, bl1);
                MMA16816(sc[nt], ql[ks], bh0, bh1);
            }
        }

        // Causal mask (diagonal tile only)
        if (kt == nkt - 1) {
            const int r0 = qrow0 + g, r1 = r0 + 8;
#pragma unroll
            for (int nt = 0; nt < 8; nt++) {
                const int c0 = k0 + nt * 8 + tg * 2;
                if (c0 > r0)     sc[nt][0] = -1e30f;
                if (c0 + 1 > r0) sc[nt][1] = -1e30f;
                if (c0 > r1)     sc[nt][2] = -1e30f;
                if (c0 + 1 > r1) sc[nt][3] = -1e30f;
            }
        }

        // Online softmax: rows g (c0,c1) and g+8 (c2,c3); 4-lane reductions.
        float mx0 = -1e30f, mx1 = -1e30f;
#pragma unroll
        for (int nt = 0; nt < 8; nt++) {
            mx0 = fmaxf(mx0, fmaxf(sc[nt][0], sc[nt][1]));
            mx1 = fmaxf(mx1, fmaxf(sc[nt][2], sc[nt][3]));
        }
        mx0 = fmaxf(mx0, __shfl_xor_sync(0xffffffffu, mx0, 1));
        mx0 = fmaxf(mx0, __shfl_xor_sync(0xffffffffu, mx0, 2));
        mx1 = fmaxf(mx1, __shfl_xor_sync(0xffffffffu, mx1, 1));
        mx1 = fmaxf(mx1, __shfl_xor_sync(0xffffffffu, mx1, 2));
        const float nm0 = fmaxf(m0, mx0);
        const float nm1 = fmaxf(m1, mx1);
        const float al0 = __expf(m0 - nm0);
        const float al1 = __expf(m1 - nm1);
        m0 = nm0; m1 = nm1;

        float s0 = 0.f, s1 = 0.f;
        uint32_t pf[8][4];   // per nt: {hi01, lo01, hi23, lo23}
#pragma unroll
        for (int nt = 0; nt < 8; nt++) {
            const float p0 = __expf(sc[nt][0] - nm0);
            const float p1 = __expf(sc[nt][1] - nm0);
            const float p2 = __expf(sc[nt][2] - nm1);
            const float p3 = __expf(sc[nt][3] - nm1);
            s0 += p0 + p1;
            s1 += p2 + p3;
            split2(p0, p1, pf[nt][0], pf[nt][1]);
            split2(p2, p3, pf[nt][2], pf[nt][3]);
        }
        s0 += __shfl_xor_sync(0xffffffffu, s0, 1);
        s0 += __shfl_xor_sync(0xffffffffu, s0, 2);
        s1 += __shfl_xor_sync(0xffffffffu, s1, 1);
        s1 += __shfl_xor_sync(0xffffffffu, s1, 2);
        l0 = l0 * al0 + s0;
        l1 = l1 * al1 + s1;
#pragma unroll
        for (int nt = 0; nt < 16; nt++) {
            o[nt][0] *= al0; o[nt][1] *= al0;
            o[nt][2] *= al1; o[nt][3] *= al1;
        }

        // O += P V  (P fragments already in A layout)
#pragma unroll
        for (int kk = 0; kk < 4; kk++) {
            const uint32_t aH[4] = {pf[2 * kk][0], pf[2 * kk][2],
                                    pf[2 * kk + 1][0], pf[2 * kk + 1][2]};
            const uint32_t aL[4] = {pf[2 * kk][1], pf[2 * kk][3],
                                    pf[2 * kk + 1][1], pf[2 * kk + 1][3]};
            const int kc = kk * 16 + tg * 2;
#pragma unroll
            for (int nt = 0; nt < 16; nt++) {
                const int r = nt * 8 + g;
                const unsigned short* pb = VH + r * VST + kc;
                const uint32_t bh0 = *(const uint32_t*)(pb);
                const uint32_t bh1 = *(const uint32_t*)(pb + 8);
                const unsigned short* pl = VL + r * VST + kc;
                const uint32_t bl0 = *(const uint32_t*)(pl);
                const uint32_t bl1 = *(const uint32_t*)(pl + 8);
                MMA16816(o[nt], aH, bh0, bh1);
                MMA16816(o[nt], aH, bl0, bl1);
                MMA16816(o[nt], aL, bh0, bh1);
            }
        }
    }

    // Epilogue: normalize by l, softmax over head dim (128 cols), write.
    const float inv0 = 1.f / l0;
    const float inv1 = 1.f / l1;
#pragma unroll
    for (int nt = 0; nt < 16; nt++) {
        o[nt][0] *= inv0; o[nt][1] *= inv0;
        o[nt][2] *= inv1; o[nt][3] *= inv1;
    }
    float mxA = -1e30f, mxB = -1e30f;
#pragma unroll
    for (int nt = 0; nt < 16; nt++) {
        mxA = fmaxf(mxA, fmaxf(o[nt][0], o[nt][1]));
        mxB = fmaxf(mxB, fmaxf(o[nt][2], o[nt][3]));
    }
    mxA = fmaxf(mxA, __shfl_xor_sync(0xffffffffu, mxA, 1));
    mxA = fmaxf(mxA, __shfl_xor_sync(0xffffffffu, mxA, 2));
    mxB = fmaxf(mxB, __shfl_xor_sync(0xffffffffu, mxB, 1));
    mxB = fmaxf(mxB, __shfl_xor_sync(0xffffffffu, mxB, 2));
    float sA = 0.f, sB = 0.f;
#pragma unroll
    for (int nt = 0; nt < 16; nt++) {
        o[nt][0] = __expf(o[nt][0] - mxA);
        o[nt][1] = __expf(o[nt][1] - mxA);
        o[nt][2] = __expf(o[nt][2] - mxB);
        o[nt][3] = __expf(o[nt][3] - mxB);
        sA += o[nt][0] + o[nt][1];
        sB += o[nt][2] + o[nt][3];
    }
    sA += __shfl_xor_sync(0xffffffffu, sA, 1);
    sA += __shfl_xor_sync(0xffffffffu, sA, 2);
    sB += __shfl_xor_sync(0xffffffffu, sB, 1);
    sB += __shfl_xor_sync(0xffffffffu, sB, 2);
    const float iA = 1.f / sA;
    const float iB = 1.f / sB;

    const int r0 = qrow0 + g;
    const int r1 = r0 + 8;
    float* op0 = out + ((size_t)b * S_ + r0) * D_ + h * DH_;
    float* op1 = out + ((size_t)b * S_ + r1) * D_ + h * DH_;
#pragma unroll
    for (int nt = 0; nt < 16; nt++) {
        const int d = nt * 8 + tg * 2;
        float2 wA; wA.x = o[nt][0] * iA; wA.y = o[nt][1] * iA;
        float2 wB; wB.x = o[nt][2] * iB; wB.y = o[nt][3] * iB;
        *(float2*)(op0 + d) = wA;
        *(float2*)(op1 + d) = wB;
    }
}

// ---------------------------------------------------------------------------
extern "C" void kernel_launch(void* const* d_in, const int* in_sizes, int n_in,
                              void* d_out, int out_size)
{
    (void)in_sizes; (void)n_in; (void)out_size;
    const float* x  = (const float*)d_in[0];
    const float* wq = (const float*)d_in[1];
    const float* wk = (const float*)d_in[2];
    const float* wv = (const float*)d_in[3];
    const float* rc = (const float*)d_in[4];
    const float* rs = (const float*)d_in[5];
    float* out = (float*)d_out;

    cudaFuncSetAttribute(proj_mma_kernel,
                         cudaFuncAttributeMaxDynamicSharedMemorySize, PROJ_SMEM);
    cudaFuncSetAttribute(fa_mma_kernel,
                         cudaFuncAttributeMaxDynamicSharedMemorySize, FA_SMEM_B);

    dim3 pg(D_ / 256, (B_ * S_) / 128, 3);
    proj_mma_kernel<<<pg, 256, PROJ_SMEM>>>(x, wq, wk, wv, rc, rs);

    dim3 fg(S_ / 64, B_ * H_);
    fa_mma_kernel<<<fg, 128, FA_SMEM_B>>>(out);
}

// round 11
// speedup vs baseline: 2.6949x; 1.1353x over previous
#include <cuda_runtime.h>
#include <cuda_bf16.h>
#include <cstdint>

#define B_ 2
#define S_ 2048
#define D_ 2048
#define H_ 16
#define DH_ 128

// Q kept fp32 (RoPE'd, scaled). K/V stored pre-split bf16 hi/lo.
__device__ float g_Q[(size_t)B_ * H_ * S_ * DH_];
__device__ unsigned short g_KH[(size_t)B_ * H_ * S_ * DH_];  // [bh][s][d]
__device__ unsigned short g_KL[(size_t)B_ * H_ * S_ * DH_];
__device__ unsigned short g_VH[(size_t)B_ * H_ * DH_ * S_];  // [bh][d][s]
__device__ unsigned short g_VL[(size_t)B_ * H_ * DH_ * S_];
// Pre-split inputs: x and packed W (q,k,v).
__device__ unsigned short g_xh[(size_t)B_ * S_ * D_];
__device__ unsigned short g_xl[(size_t)B_ * S_ * D_];
__device__ unsigned short g_wh[(size_t)3 * D_ * D_];
__device__ unsigned short g_wl[(size_t)3 * D_ * D_];

#define MMA16816(d, a, b0v, b1v)                                               \
    asm volatile(                                                              \
        "mma.sync.aligned.m16n8k16.row.col.f32.bf16.bf16.f32 "                 \
        "{%0,%1,%2,%3}, {%4,%5,%6,%7}, {%8,%9}, {%0,%1,%2,%3};"                \
        : "+f"((d)[0]), "+f"((d)[1]), "+f"((d)[2]), "+f"((d)[3])               \
        : "r"((a)[0]), "r"((a)[1]), "r"((a)[2]), "r"((a)[3]),                  \
          "r"(b0v), "r"(b1v))

static __device__ __forceinline__ void split4(float4 v, uint2& hi, uint2& lo) {
    __nv_bfloat16 h0 = __float2bfloat16(v.x);
    __nv_bfloat16 h1 = __float2bfloat16(v.y);
    __nv_bfloat16 h2 = __float2bfloat16(v.z);
    __nv_bfloat16 h3 = __float2bfloat16(v.w);
    __nv_bfloat16 l0 = __float2bfloat16(v.x - __bfloat162float(h0));
    __nv_bfloat16 l1 = __float2bfloat16(v.y - __bfloat162float(h1));
    __nv_bfloat16 l2 = __float2bfloat16(v.z - __bfloat162float(h2));
    __nv_bfloat16 l3 = __float2bfloat16(v.w - __bfloat162float(h3));
    hi.x = ((uint32_t)__bfloat16_as_ushort(h1) << 16) | __bfloat16_as_ushort(h0);
    hi.y = ((uint32_t)__bfloat16_as_ushort(h3) << 16) | __bfloat16_as_ushort(h2);
    lo.x = ((uint32_t)__bfloat16_as_ushort(l1) << 16) | __bfloat16_as_ushort(l0);
    lo.y = ((uint32_t)__bfloat16_as_ushort(l3) << 16) | __bfloat16_as_ushort(l2);
}
static __device__ __forceinline__ void split2(float x, float y,
                                              uint32_t& hi, uint32_t& lo) {
    __nv_bfloat16 hx = __float2bfloat16(x);
    __nv_bfloat16 hy = __float2bfloat16(y);
    __nv_bfloat16 lx = __float2bfloat16(x - __bfloat162float(hx));
    __nv_bfloat16 ly = __float2bfloat16(y - __bfloat162float(hy));
    hi = ((uint32_t)__bfloat16_as_ushort(hy) << 16) | __bfloat16_as_ushort(hx);
    lo = ((uint32_t)__bfloat16_as_ushort(ly) << 16) | __bfloat16_as_ushort(lx);
}

// ===========================================================================
// Kernel 0: pre-split x and W into bf16 hi/lo (convert once, reuse many).
// blockIdx.y: 0 = x, 1..3 = wq/wk/wv.
// ===========================================================================
__global__ __launch_bounds__(256) void presplit_kernel(
    const float* __restrict__ x,
    const float* __restrict__ wq,
    const float* __restrict__ wk,
    const float* __restrict__ wv)
{
    const int which = blockIdx.y;
    const float* __restrict__ src =
        (which == 0) ? x : ((which == 1) ? wq : ((which == 2) ? wk : wv));
    unsigned short* dh = (which == 0) ? g_xh : g_wh + (size_t)(which - 1) * D_ * D_;
    unsigned short* dl = (which == 0) ? g_xl : g_wl + (size_t)(which - 1) * D_ * D_;
    const size_t n4 =
        ((which == 0) ? (size_t)B_ * S_ * D_ : (size_t)D_ * D_) / 4;
    for (size_t i = (size_t)blockIdx.x * blockDim.x + threadIdx.x; i < n4;
         i += (size_t)gridDim.x * blockDim.x) {
        float4 v = ((const float4*)src)[i];
        uint2 hi, lo;
        split4(v, hi, lo);
        ((uint2*)dh)[i] = hi;
        ((uint2*)dl)[i] = lo;
    }
}

// ===========================================================================
// Kernel 1: QKV projection via mma.sync bf16 (hi/lo split) + fused RoPE.
// Fill is a pure bf16 copy from pre-split globals.
// Epilogue: Q -> f32; K -> RoPE'd bf16 hi/lo [bh][s][d];
//           V -> bf16 hi/lo transposed [bh][d][s].
// ===========================================================================
#define KC 32
#define NCH (D_ / KC)            // 64
#define AST 40
#define OFF_AH 0
#define OFF_AL (128 * AST)
#define OFF_BH (2 * 128 * AST)
#define OFF_BL (OFF_BH + 256 * AST)
#define STG_ELEMS (OFF_BL + 256 * AST)
#define PROJ_SMEM (2 * STG_ELEMS * 2)

__global__ __launch_bounds__(256) void proj_mma_kernel(
    const float* __restrict__ rcos,
    const float* __restrict__ rsin)
{
    extern __shared__ unsigned short psm[];

    const int mode = blockIdx.z;
    const unsigned short* __restrict__ wh = g_wh + (size_t)mode * D_ * D_;
    const unsigned short* __restrict__ wl = g_wl + (size_t)mode * D_ * D_;

    const int m0 = blockIdx.y * 128;
    const int n0 = blockIdx.x * 256;
    const int t = threadIdx.x;
    const int lane = t & 31;
    const int wid = t >> 5;
    const int wm = wid & 1;
    const int wn = wid >> 1;
    const int g = lane >> 2;
    const int tg = lane & 3;

    float acc[4][8][4];
#pragma unroll
    for (int mt = 0; mt < 4; mt++)
#pragma unroll
        for (int nt = 0; nt < 8; nt++)
#pragma unroll
            for (int c = 0; c < 4; c++) acc[mt][nt][c] = 0.f;

    const int frow = t >> 3;
    const int fcol = (t & 7) * 4;

    auto fill = [&](int ic, int st) {
        unsigned short* sb = psm + st * STG_ELEMS;
        const int k0 = ic * KC;
#pragma unroll
        for (int p = 0; p < 4; p++) {
            const int row = frow + p * 32;
            const size_t go = (size_t)(m0 + row) * D_ + k0 + fcol;
            *(uint2*)(sb + OFF_AH + row * AST + fcol) = *(const uint2*)(g_xh + go);
            *(uint2*)(sb + OFF_AL + row * AST + fcol) = *(const uint2*)(g_xl + go);
        }
#pragma unroll
        for (int p = 0; p < 8; p++) {
            const int row = frow + p * 32;
            const size_t go = (size_t)(n0 + row) * D_ + k0 + fcol;
            *(uint2*)(sb + OFF_BH + row * AST + fcol) = *(const uint2*)(wh + go);
            *(uint2*)(sb + OFF_BL + row * AST + fcol) = *(const uint2*)(wl + go);
        }
    };

    auto compute = [&](int st) {
        const unsigned short* sb = psm + st * STG_ELEMS;
#pragma unroll
        for (int ks = 0; ks < 2; ks++) {
            const int kc = ks * 16 + tg * 2;
            uint32_t ah[4][4], al[4][4];
#pragma unroll
            for (int mt = 0; mt < 4; mt++) {
                const int r = wm * 64 + mt * 16 + g;
                const unsigned short* pa = sb + OFF_AH + r * AST + kc;
                ah[mt][0] = *(const uint32_t*)(pa);
                ah[mt][1] = *(const uint32_t*)(pa + 8 * AST);
                ah[mt][2] = *(const uint32_t*)(pa + 8);
                ah[mt][3] = *(const uint32_t*)(pa + 8 * AST + 8);
                const unsigned short* pl = sb + OFF_AL + r * AST + kc;
                al[mt][0] = *(const uint32_t*)(pl);
                al[mt][1] = *(const uint32_t*)(pl + 8 * AST);
                al[mt][2] = *(const uint32_t*)(pl + 8);
                al[mt][3] = *(const uint32_t*)(pl + 8 * AST + 8);
            }
#pragma unroll
            for (int nt = 0; nt < 8; nt++) {
                const int r = wn * 64 + nt * 8 + g;
                const unsigned short* pb = sb + OFF_BH + r * AST + kc;
                const uint32_t bh0 = *(const uint32_t*)(pb);
                const uint32_t bh1 = *(const uint32_t*)(pb + 8);
                const unsigned short* pbl = sb + OFF_BL + r * AST + kc;
                const uint32_t bl0 = *(const uint32_t*)(pbl);
                const uint32_t bl1 = *(const uint32_t*)(pbl + 8);
#pragma unroll
                for (int mt = 0; mt < 4; mt++) {
                    MMA16816(acc[mt][nt], ah[mt], bh0, bh1);
                    MMA16816(acc[mt][nt], ah[mt], bl0, bl1);
                    MMA16816(acc[mt][nt], al[mt], bh0, bh1);
                }
            }
        }
    };

    fill(0, 0);
    __syncthreads();
    for (int ic = 0; ic < NCH; ic++) {
        const int st = ic & 1;
        if (ic + 1 < NCH) fill(ic + 1, st ^ 1);
        compute(st);
        __syncthreads();
    }

    const float qscale = 0.08838834764831845f;
#pragma unroll
    for (int mt = 0; mt < 4; mt++) {
#pragma unroll
        for (int half = 0; half < 2; half++) {
            const int m = m0 + wm * 64 + mt * 16 + g + half * 8;
            const int b = m >> 11;
            const int s = m & (S_ - 1);
#pragma unroll
            for (int nt = 0; nt < 8; nt++) {
                const int n = n0 + wn * 64 + nt * 8 + tg * 2;
                const int h = n >> 7;
                const int d = n & (DH_ - 1);
                const float v0 = acc[mt][nt][half * 2];
                const float v1 = acc[mt][nt][half * 2 + 1];
                const int bh = b * H_ + h;
                if (mode == 2) {
                    // V: split + transposed store [bh][d][s]
                    const size_t tb = ((size_t)bh * DH_ + d) * S_ + s;
                    __nv_bfloat16 h0 = __float2bfloat16(v0);
                    __nv_bfloat16 h1 = __float2bfloat16(v1);
                    g_VH[tb]      = __bfloat16_as_ushort(h0);
                    g_VH[tb + S_] = __bfloat16_as_ushort(h1);
                    g_VL[tb] = __bfloat16_as_ushort(
                        __float2bfloat16(v0 - __bfloat162float(h0)));
                    g_VL[tb + S_] = __bfloat16_as_ushort(
                        __float2bfloat16(v1 - __bfloat162float(h1)));
                } else {
                    const float c0  = rcos[s * DH_ + d];
                    const float sn0 = rsin[s * DH_ + d];
                    const float c1  = rcos[s * DH_ + d + 1];
                    const float sn1 = rsin[s * DH_ + d + 1];
                    float o0 = v0 * c0 - v1 * sn0;
                    float o1 = v1 * c1 + v0 * sn1;
                    const size_t off = ((size_t)bh * S_ + s) * DH_ + d;
                    if (mode == 0) {
                        float2 st2;
                        st2.x = o0 * qscale;
                        st2.y = o1 * qscale;
                        *(float2*)(g_Q + off) = st2;
                    } else {
                        uint32_t hi, lo;
                        split2(o0, o1, hi, lo);
                        *(uint32_t*)(g_KH + off) = hi;
                        *(uint32_t*)(g_KL + off) = lo;
                    }
                }
            }
        }
    }
}

// ===========================================================================
// Kernel 2: flash attention via mma.sync bf16 hi/lo + fused second softmax.
// K/V loaders are pure coalesced uint4 copies from pre-split globals.
// ===========================================================================
#define KST 136              // K tile row stride (bf16 elems)
#define VST 72               // Vt row stride
#define FA_KH 0
#define FA_KL (64 * KST)
#define FA_VH (2 * 64 * KST)
#define FA_VL (FA_VH + 128 * VST)
#define FA_ELEMS (FA_VL + 128 * VST)
#define FA_SMEM_B (FA_ELEMS * 2)   // 71680 bytes

__global__ __launch_bounds__(128, 2) void fa_mma_kernel(float* __restrict__ out)
{
    extern __shared__ unsigned short fsm[];
    unsigned short* KH = fsm + FA_KH;
    unsigned short* KL = fsm + FA_KL;
    unsigned short* VH = fsm + FA_VH;
    unsigned short* VL = fsm + FA_VL;

    const int t = threadIdx.x;
    const int lane = t & 31;
    const int wid = t >> 5;
    const int g = lane >> 2;
    const int tg = lane & 3;
    const int bh = blockIdx.y;
    const int b = bh >> 4;
    const int h = bh & 15;
    const int q0 = ((int)gridDim.x - 1 - (int)blockIdx.x) * 64;
    const int qrow0 = q0 + wid * 16;

    const float* __restrict__ Qg = g_Q + ((size_t)bh * S_ + qrow0) * DH_;
    const unsigned short* __restrict__ KgH = g_KH + (size_t)bh * S_ * DH_;
    const unsigned short* __restrict__ KgL = g_KL + (size_t)bh * S_ * DH_;
    const unsigned short* __restrict__ VgH = g_VH + (size_t)bh * DH_ * S_;
    const unsigned short* __restrict__ VgL = g_VL + (size_t)bh * DH_ * S_;

    // Q fragments (hi/lo), register resident.
    uint32_t qh[8][4], ql[8][4];
#pragma unroll
    for (int ks = 0; ks < 8; ks++) {
        const int kc = ks * 16 + tg * 2;
        float2 v0 = *(const float2*)(Qg + (size_t)g * DH_ + kc);
        float2 v1 = *(const float2*)(Qg + (size_t)(g + 8) * DH_ + kc);
        float2 v2 = *(const float2*)(Qg + (size_t)g * DH_ + kc + 8);
        float2 v3 = *(const float2*)(Qg + (size_t)(g + 8) * DH_ + kc + 8);
        split2(v0.x, v0.y, qh[ks][0], ql[ks][0]);
        split2(v1.x, v1.y, qh[ks][1], ql[ks][1]);
        split2(v2.x, v2.y, qh[ks][2], ql[ks][2]);
        split2(v3.x, v3.y, qh[ks][3], ql[ks][3]);
    }

    float m0 = -1e30f, m1 = -1e30f, l0 = 0.f, l1 = 0.f;
    float o[16][4];
#pragma unroll
    for (int nt = 0; nt < 16; nt++)
#pragma unroll
        for (int c = 0; c < 4; c++) o[nt][c] = 0.f;

    const int nkt = (q0 >> 6) + 1;
    for (int kt = 0; kt < nkt; kt++) {
        const int k0 = kt * 64;
        __syncthreads();

        // K tile copy: 64 rows x 128 cols, uint4 (8 bf16) per access.
        {
            const int fr = t >> 4;          // 0..7
            const int fc = (t & 15) * 8;    // 0..120
#pragma unroll
            for (int p = 0; p < 8; p++) {
                const int row = fr + p * 8;
                const size_t go = (size_t)(k0 + row) * DH_ + fc;
                *(uint4*)(KH + row * KST + fc) = *(const uint4*)(KgH + go);
                *(uint4*)(KL + row * KST + fc) = *(const uint4*)(KgL + go);
            }
        }
        // V tile copy (already transposed in global): 128 d-rows x 64 s-cols.
        {
            const int fr = t >> 3;          // 0..15
            const int fc = (t & 7) * 8;     // 0..56
#pragma unroll
            for (int p = 0; p < 8; p++) {
                const int row = fr + p * 16;
                const size_t go = (size_t)row * S_ + k0 + fc;
                *(uint4*)(VH + row * VST + fc) = *(const uint4*)(VgH + go);
                *(uint4*)(VL + row * VST + fc) = *(const uint4*)(VgL + go);
            }
        }
        __syncthreads();

        // S = Q K^T (16 x 64 per warp), hi/lo compensated
        float sc[8][4];
#pragma unroll
        for (int nt = 0; nt < 8; nt++)
#pragma unroll
            for (int c = 0; c < 4; c++) sc[nt][c] = 0.f;

#pragma unroll
        for (int nt = 0; nt < 8; nt++) {
            const int r = nt * 8 + g;
#pragma unroll
            for (int ks = 0; ks < 8; ks++) {
                const int kc = ks * 16 + tg * 2;
                const unsigned short* pb = KH + r * KST + kc;
                const uint32_t bh0 = *(const uint32_t*)(pb);
                const uint32_t bh1 = *(const uint32_t*)(pb + 8);
                const unsigned short* pl = KL + r * KST + kc;
                const uint32_t bl0 = *(const uint32_t*)(pl);
                const uint32_t bl1 = *(const uint32_t*)(pl + 8);
                MMA16816(sc[nt], qh[ks], bh0, bh1);
                MMA16816(sc[nt], qh[ks], bl0, bl1);
                MMA16816(sc[nt], ql[ks], bh0, bh1);
            }
        }

        // Causal mask (diagonal tile only)
        if (kt == nkt - 1) {
            const int r0 = qrow0 + g, r1 = r0 + 8;
#pragma unroll
            for (int nt = 0; nt < 8; nt++) {
                const int c0 = k0 + nt * 8 + tg * 2;
                if (c0 > r0)     sc[nt][0] = -1e30f;
                if (c0 + 1 > r0) sc[nt][1] = -1e30f;
                if (c0 > r1)     sc[nt][2] = -1e30f;
                if (c0 + 1 > r1) sc[nt][3] = -1e30f;
            }
        }

        // Online softmax: rows g (c0,c1) and g+8 (c2,c3); 4-lane reductions.
        float mx0 = -1e30f, mx1 = -1e30f;
#pragma unroll
        for (int nt = 0; nt < 8; nt++) {
            mx0 = fmaxf(mx0, fmaxf(sc[nt][0], sc[nt][1]));
            mx1 = fmaxf(mx1, fmaxf(sc[nt][2], sc[nt][3]));
        }
        mx0 = fmaxf(mx0, __shfl_xor_sync(0xffffffffu, mx0, 1));
        mx0 = fmaxf(mx0, __shfl_xor_sync(0xffffffffu, mx0, 2));
        mx1 = fmaxf(mx1, __shfl_xor_sync(0xffffffffu, mx1, 1));
        mx1 = fmaxf(mx1, __shfl_xor_sync(0xffffffffu, mx1, 2));
        const float nm0 = fmaxf(m0, mx0);
        const float nm1 = fmaxf(m1, mx1);
        const float al0 = __expf(m0 - nm0);
        const float al1 = __expf(m1 - nm1);
        m0 = nm0; m1 = nm1;

        float s0 = 0.f, s1 = 0.f;
        uint32_t pf[8][4];   // per nt: {hi01, lo01, hi23, lo23}
#pragma unroll
        for (int nt = 0; nt < 8; nt++) {
            const float p0 = __expf(sc[nt][0] - nm0);
            const float p1 = __expf(sc[nt][1] - nm0);
            const float p2 = __expf(sc[nt][2] - nm1);
            const float p3 = __expf(sc[nt][3] - nm1);
            s0 += p0 + p1;
            s1 += p2 + p3;
            split2(p0, p1, pf[nt][0], pf[nt][1]);
            split2(p2, p3, pf[nt][2], pf[nt][3]);
        }
        s0 += __shfl_xor_sync(0xffffffffu, s0, 1);
        s0 += __shfl_xor_sync(0xffffffffu, s0, 2);
        s1 += __shfl_xor_sync(0xffffffffu, s1, 1);
        s1 += __shfl_xor_sync(0xffffffffu, s1, 2);
        l0 = l0 * al0 + s0;
        l1 = l1 * al1 + s1;
#pragma unroll
        for (int nt = 0; nt < 16; nt++) {
            o[nt][0] *= al0; o[nt][1] *= al0;
            o[nt][2] *= al1; o[nt][3] *= al1;
        }

        // O += P V  (P fragments already in A layout)
#pragma unroll
        for (int kk = 0; kk < 4; kk++) {
            const uint32_t aH[4] = {pf[2 * kk][0], pf[2 * kk][2],
                                    pf[2 * kk + 1][0], pf[2 * kk + 1][2]};
            const uint32_t aL[4] = {pf[2 * kk][1], pf[2 * kk][3],
                                    pf[2 * kk + 1][1], pf[2 * kk + 1][3]};
            const int kc = kk * 16 + tg * 2;
#pragma unroll
            for (int nt = 0; nt < 16; nt++) {
                const int r = nt * 8 + g;
                const unsigned short* pb = VH + r * VST + kc;
                const uint32_t bh0 = *(const uint32_t*)(pb);
                const uint32_t bh1 = *(const uint32_t*)(pb + 8);
                const unsigned short* pl = VL + r * VST + kc;
                const uint32_t bl0 = *(const uint32_t*)(pl);
                const uint32_t bl1 = *(const uint32_t*)(pl + 8);
                MMA16816(o[nt], aH, bh0, bh1);
                MMA16816(o[nt], aH, bl0, bl1);
                MMA16816(o[nt], aL, bh0, bh1);
            }
        }
    }

    // Epilogue: normalize by l, softmax over head dim (128 cols), write.
    const float inv0 = 1.f / l0;
    const float inv1 = 1.f / l1;
#pragma unroll
    for (int nt = 0; nt < 16; nt++) {
        o[nt][0] *= inv0; o[nt][1] *= inv0;
        o[nt][2] *= inv1; o[nt][3] *= inv1;
    }
    float mxA = -1e30f, mxB = -1e30f;
#pragma unroll
    for (int nt = 0; nt < 16; nt++) {
        mxA = fmaxf(mxA, fmaxf(o[nt][0], o[nt][1]));
        mxB = fmaxf(mxB, fmaxf(o[nt][2], o[nt][3]));
    }
    mxA = fmaxf(mxA, __shfl_xor_sync(0xffffffffu, mxA, 1));
    mxA = fmaxf(mxA, __shfl_xor_sync(0xffffffffu, mxA, 2));
    mxB = fmaxf(mxB, __shfl_xor_sync(0xffffffffu, mxB, 1));
    mxB = fmaxf(mxB, __shfl_xor_sync(0xffffffffu, mxB, 2));
    float sA = 0.f, sB = 0.f;
#pragma unroll
    for (int nt = 0; nt < 16; nt++) {
        o[nt][0] = __expf(o[nt][0] - mxA);
        o[nt][1] = __expf(o[nt][1] - mxA);
        o[nt][2] = __expf(o[nt][2] - mxB);
        o[nt][3] = __expf(o[nt][3] - mxB);
        sA += o[nt][0] + o[nt][1];
        sB += o[nt][2] + o[nt][3];
    }
    sA += __shfl_xor_sync(0xffffffffu, sA, 1);
    sA += __shfl_xor_sync(0xffffffffu, sA, 2);
    sB += __shfl_xor_sync(0xffffffffu, sB, 1);
    sB += __shfl_xor_sync(0xffffffffu, sB, 2);
    const float iA = 1.f / sA;
    const float iB = 1.f / sB;

    const int r0 = qrow0 + g;
    const int r1 = r0 + 8;
    float* op0 = out + ((size_t)b * S_ + r0) * D_ + h * DH_;
    float* op1 = out + ((size_t)b * S_ + r1) * D_ + h * DH_;
#pragma unroll
    for (int nt = 0; nt < 16; nt++) {
        const int d = nt * 8 + tg * 2;
        float2 wA; wA.x = o[nt][0] * iA; wA.y = o[nt][1] * iA;
        float2 wB; wB.x = o[nt][2] * iB; wB.y = o[nt][3] * iB;
        *(float2*)(op0 + d) = wA;
        *(float2*)(op1 + d) = wB;
    }
}

// ---------------------------------------------------------------------------
extern "C" void kernel_launch(void* const* d_in, const int* in_sizes, int n_in,
                              void* d_out, int out_size)
{
    (void)in_sizes; (void)n_in; (void)out_size;
    const float* x  = (const float*)d_in[0];
    const float* wq = (const float*)d_in[1];
    const float* wk = (const float*)d_in[2];
    const float* wv = (const float*)d_in[3];
    const float* rc = (const float*)d_in[4];
    const float* rs = (const float*)d_in[5];
    float* out = (float*)d_out;

    cudaFuncSetAttribute(proj_mma_kernel,
                         cudaFuncAttributeMaxDynamicSharedMemorySize, PROJ_SMEM);
    cudaFuncSetAttribute(fa_mma_kernel,
                         cudaFuncAttributeMaxDynamicSharedMemorySize, FA_SMEM_B);

    dim3 sg(264, 4);
    presplit_kernel<<<sg, 256>>>(x, wq, wk, wv);

    dim3 pg(D_ / 256, (B_ * S_) / 128, 3);
    proj_mma_kernel<<<pg, 256, PROJ_SMEM>>>(rc, rs);

    dim3 fg(S_ / 64, B_ * H_);
    fa_mma_kernel<<<fg, 128, FA_SMEM_B>>>(out);
}

// round 13
// speedup vs baseline: 2.9256x; 1.0856x over previous
#include <cuda_runtime.h>
#include <cuda_bf16.h>
#include <cstdint>

#define B_ 2
#define S_ 2048
#define D_ 2048
#define H_ 16
#define DH_ 128

// Q kept fp32 (RoPE'd, scaled). K/V stored pre-split bf16 hi/lo.
__device__ float g_Q[(size_t)B_ * H_ * S_ * DH_];
__device__ unsigned short g_KH[(size_t)B_ * H_ * S_ * DH_];  // [bh][s][d]
__device__ unsigned short g_KL[(size_t)B_ * H_ * S_ * DH_];
__device__ unsigned short g_VH[(size_t)B_ * H_ * DH_ * S_];  // [bh][d][s]
__device__ unsigned short g_VL[(size_t)B_ * H_ * DH_ * S_];
// Pre-split inputs: x and packed W (q,k,v).
__device__ unsigned short g_xh[(size_t)B_ * S_ * D_];
__device__ unsigned short g_xl[(size_t)B_ * S_ * D_];
__device__ unsigned short g_wh[(size_t)3 * D_ * D_];
__device__ unsigned short g_wl[(size_t)3 * D_ * D_];

#define MMA16816(d, a, b0v, b1v)                                               \
    asm volatile(                                                              \
        "mma.sync.aligned.m16n8k16.row.col.f32.bf16.bf16.f32 "                 \
        "{%0,%1,%2,%3}, {%4,%5,%6,%7}, {%8,%9}, {%0,%1,%2,%3};"                \
        : "+f"((d)[0]), "+f"((d)[1]), "+f"((d)[2]), "+f"((d)[3])               \
        : "r"((a)[0]), "r"((a)[1]), "r"((a)[2]), "r"((a)[3]),                  \
          "r"(b0v), "r"(b1v))

#define CP_ASYNC16(dst_u32, src_ptr)                                           \
    asm volatile("cp.async.cg.shared.global [%0], [%1], 16;"                   \
                 :: "r"(dst_u32), "l"(src_ptr) : "memory")
#define CP_COMMIT() asm volatile("cp.async.commit_group;" ::: "memory")
#define CP_WAIT(N)  asm volatile("cp.async.wait_group %0;" :: "n"(N) : "memory")

static __device__ __forceinline__ uint32_t smem_u32(const void* p) {
    return (uint32_t)__cvta_generic_to_shared(p);
}

static __device__ __forceinline__ void split4(float4 v, uint2& hi, uint2& lo) {
    __nv_bfloat16 h0 = __float2bfloat16(v.x);
    __nv_bfloat16 h1 = __float2bfloat16(v.y);
    __nv_bfloat16 h2 = __float2bfloat16(v.z);
    __nv_bfloat16 h3 = __float2bfloat16(v.w);
    __nv_bfloat16 l0 = __float2bfloat16(v.x - __bfloat162float(h0));
    __nv_bfloat16 l1 = __float2bfloat16(v.y - __bfloat162float(h1));
    __nv_bfloat16 l2 = __float2bfloat16(v.z - __bfloat162float(h2));
    __nv_bfloat16 l3 = __float2bfloat16(v.w - __bfloat162float(h3));
    hi.x = ((uint32_t)__bfloat16_as_ushort(h1) << 16) | __bfloat16_as_ushort(h0);
    hi.y = ((uint32_t)__bfloat16_as_ushort(h3) << 16) | __bfloat16_as_ushort(h2);
    lo.x = ((uint32_t)__bfloat16_as_ushort(l1) << 16) | __bfloat16_as_ushort(l0);
    lo.y = ((uint32_t)__bfloat16_as_ushort(l3) << 16) | __bfloat16_as_ushort(l2);
}
static __device__ __forceinline__ void split2(float x, float y,
                                              uint32_t& hi, uint32_t& lo) {
    __nv_bfloat16 hx = __float2bfloat16(x);
    __nv_bfloat16 hy = __float2bfloat16(y);
    __nv_bfloat16 lx = __float2bfloat16(x - __bfloat162float(hx));
    __nv_bfloat16 ly = __float2bfloat16(y - __bfloat162float(hy));
    hi = ((uint32_t)__bfloat16_as_ushort(hy) << 16) | __bfloat16_as_ushort(hx);
    lo = ((uint32_t)__bfloat16_as_ushort(ly) << 16) | __bfloat16_as_ushort(lx);
}

// ===========================================================================
// Kernel 0: pre-split x and W into bf16 hi/lo (convert once, reuse many).
// ===========================================================================
__global__ __launch_bounds__(256) void presplit_kernel(
    const float* __restrict__ x,
    const float* __restrict__ wq,
    const float* __restrict__ wk,
    const float* __restrict__ wv)
{
    const int which = blockIdx.y;
    const float* __restrict__ src =
        (which == 0) ? x : ((which == 1) ? wq : ((which == 2) ? wk : wv));
    unsigned short* dh = (which == 0) ? g_xh : g_wh + (size_t)(which - 1) * D_ * D_;
    unsigned short* dl = (which == 0) ? g_xl : g_wl + (size_t)(which - 1) * D_ * D_;
    const size_t n4 =
        ((which == 0) ? (size_t)B_ * S_ * D_ : (size_t)D_ * D_) / 4;
    for (size_t i = (size_t)blockIdx.x * blockDim.x + threadIdx.x; i < n4;
         i += (size_t)gridDim.x * blockDim.x) {
        float4 v = ((const float4*)src)[i];
        uint2 hi, lo;
        split4(v, hi, lo);
        ((uint2*)dh)[i] = hi;
        ((uint2*)dl)[i] = lo;
    }
}

// ===========================================================================
// Kernel 1: QKV projection via mma.sync bf16 (hi/lo split) + fused RoPE.
// cp.async double-buffered fill (16B ops, no registers, no STS scoreboards).
// ===========================================================================
#define KC 32
#define NCH (D_ / KC)            // 64
#define AST 40
#define OFF_AH 0
#define OFF_AL (128 * AST)
#define OFF_BH (2 * 128 * AST)
#define OFF_BL (OFF_BH + 256 * AST)
#define STG_ELEMS (OFF_BL + 256 * AST)
#define PROJ_SMEM (2 * STG_ELEMS * 2)

__global__ __launch_bounds__(256) void proj_mma_kernel(
    const float* __restrict__ rcos,
    const float* __restrict__ rsin)
{
    extern __shared__ unsigned short psm[];
    const uint32_t psm_u32 = smem_u32(psm);

    const int mode = blockIdx.z;
    const unsigned short* __restrict__ wh = g_wh + (size_t)mode * D_ * D_;
    const unsigned short* __restrict__ wl = g_wl + (size_t)mode * D_ * D_;

    const int m0 = blockIdx.y * 128;
    const int n0 = blockIdx.x * 256;
    const int t = threadIdx.x;
    const int lane = t & 31;
    const int wid = t >> 5;
    const int wm = wid & 1;
    const int wn = wid >> 1;
    const int g = lane >> 2;
    const int tg = lane & 3;

    float acc[4][8][4];
#pragma unroll
    for (int mt = 0; mt < 4; mt++)
#pragma unroll
        for (int nt = 0; nt < 8; nt++)
#pragma unroll
            for (int c = 0; c < 4; c++) acc[mt][nt][c] = 0.f;

    // Async fill: 16B segments. A: 128 rows x 4 segs; B: 256 rows x 4 segs.
    auto fill_async = [&](int ic, int st) {
        const uint32_t sb = psm_u32 + (uint32_t)(st * STG_ELEMS) * 2;
        const int k0 = ic * KC;
#pragma unroll
        for (int p = 0; p < 2; p++) {
            const int idx = t + p * 256;
            const int row = idx >> 2;
            const int sg = idx & 3;
            const size_t go = (size_t)(m0 + row) * D_ + k0 + sg * 8;
            const uint32_t so = (uint32_t)(row * AST + sg * 8) * 2;
            CP_ASYNC16(sb + OFF_AH * 2 + so, g_xh + go);
            CP_ASYNC16(sb + OFF_AL * 2 + so, g_xl + go);
        }
#pragma unroll
        for (int p = 0; p < 4; p++) {
            const int idx = t + p * 256;
            const int row = idx >> 2;
            const int sg = idx & 3;
            const size_t go = (size_t)(n0 + row) * D_ + k0 + sg * 8;
            const uint32_t so = (uint32_t)(row * AST + sg * 8) * 2;
            CP_ASYNC16(sb + OFF_BH * 2 + so, wh + go);
            CP_ASYNC16(sb + OFF_BL * 2 + so, wl + go);
        }
    };

    auto compute = [&](int st) {
        const unsigned short* sb = psm + st * STG_ELEMS;
#pragma unroll
        for (int ks = 0; ks < 2; ks++) {
            const int kc = ks * 16 + tg * 2;
            uint32_t ah[4][4], al[4][4];
#pragma unroll
            for (int mt = 0; mt < 4; mt++) {
                const int r = wm * 64 + mt * 16 + g;
                const unsigned short* pa = sb + OFF_AH + r * AST + kc;
                ah[mt][0] = *(const uint32_t*)(pa);
                ah[mt][1] = *(const uint32_t*)(pa + 8 * AST);
                ah[mt][2] = *(const uint32_t*)(pa + 8);
                ah[mt][3] = *(const uint32_t*)(pa + 8 * AST + 8);
                const unsigned short* pl = sb + OFF_AL + r * AST + kc;
                al[mt][0] = *(const uint32_t*)(pl);
                al[mt][1] = *(const uint32_t*)(pl + 8 * AST);
                al[mt][2] = *(const uint32_t*)(pl + 8);
                al[mt][3] = *(const uint32_t*)(pl + 8 * AST + 8);
            }
#pragma unroll
            for (int nt = 0; nt < 8; nt++) {
                const int r = wn * 64 + nt * 8 + g;
                const unsigned short* pb = sb + OFF_BH + r * AST + kc;
                const uint32_t bh0 = *(const uint32_t*)(pb);
                const uint32_t bh1 = *(const uint32_t*)(pb + 8);
                const unsigned short* pbl = sb + OFF_BL + r * AST + kc;
                const uint32_t bl0 = *(const uint32_t*)(pbl);
                const uint32_t bl1 = *(const uint32_t*)(pbl + 8);
#pragma unroll
                for (int mt = 0; mt < 4; mt++) {
                    MMA16816(acc[mt][nt], ah[mt], bh0, bh1);
                    MMA16816(acc[mt][nt], ah[mt], bl0, bl1);
                    MMA16816(acc[mt][nt], al[mt], bh0, bh1);
                }
            }
        }
    };

    fill_async(0, 0);
    CP_COMMIT();
    for (int ic = 0; ic < NCH; ic++) {
        const int st = ic & 1;
        if (ic + 1 < NCH) {
            fill_async(ic + 1, st ^ 1);
            CP_COMMIT();
            CP_WAIT(1);
        } else {
            CP_WAIT(0);
        }
        __syncthreads();
        compute(st);
        __syncthreads();   // all readers done before next fill overwrites
    }

    const float qscale = 0.08838834764831845f;
#pragma unroll
    for (int mt = 0; mt < 4; mt++) {
#pragma unroll
        for (int half = 0; half < 2; half++) {
            const int m = m0 + wm * 64 + mt * 16 + g + half * 8;
            const int b = m >> 11;
            const int s = m & (S_ - 1);
#pragma unroll
            for (int nt = 0; nt < 8; nt++) {
                const int n = n0 + wn * 64 + nt * 8 + tg * 2;
                const int h = n >> 7;
                const int d = n & (DH_ - 1);
                const float v0 = acc[mt][nt][half * 2];
                const float v1 = acc[mt][nt][half * 2 + 1];
                const int bh = b * H_ + h;
                if (mode == 2) {
                    const size_t tb = ((size_t)bh * DH_ + d) * S_ + s;
                    __nv_bfloat16 h0 = __float2bfloat16(v0);
                    __nv_bfloat16 h1 = __float2bfloat16(v1);
                    g_VH[tb]      = __bfloat16_as_ushort(h0);
                    g_VH[tb + S_] = __bfloat16_as_ushort(h1);
                    g_VL[tb] = __bfloat16_as_ushort(
                        __float2bfloat16(v0 - __bfloat162float(h0)));
                    g_VL[tb + S_] = __bfloat16_as_ushort(
                        __float2bfloat16(v1 - __bfloat162float(h1)));
                } else {
                    const float c0  = rcos[s * DH_ + d];
                    const float sn0 = rsin[s * DH_ + d];
                    const float c1  = rcos[s * DH_ + d + 1];
                    const float sn1 = rsin[s * DH_ + d + 1];
                    float o0 = v0 * c0 - v1 * sn0;
                    float o1 = v1 * c1 + v0 * sn1;
                    const size_t off = ((size_t)bh * S_ + s) * DH_ + d;
                    if (mode == 0) {
                        float2 st2;
                        st2.x = o0 * qscale;
                        st2.y = o1 * qscale;
                        *(float2*)(g_Q + off) = st2;
                    } else {
                        uint32_t hi, lo;
                        split2(o0, o1, hi, lo);
                        *(uint32_t*)(g_KH + off) = hi;
                        *(uint32_t*)(g_KL + off) = lo;
                    }
                }
            }
        }
    }
}

// ===========================================================================
// Kernel 2: flash attention, cp.async pipelined: K double-buffered (2 stages),
// V async single-buffered. Tensor work overlaps next-tile fetch.
// ===========================================================================
#define KST 136              // K tile row stride (bf16 elems)
#define VST 72               // Vt row stride
#define KSTAGE (2 * 64 * KST)             // one K stage (hi+lo), elems
#define FA_V0 (2 * KSTAGE)                // V base after 2 K stages
#define FA_ELEMS (FA_V0 + 2 * 128 * VST)  // 53248 elems
#define FA_SMEM_B (FA_ELEMS * 2)          // 106496 bytes

__global__ __launch_bounds__(128, 2) void fa_mma_kernel(float* __restrict__ out)
{
    extern __shared__ unsigned short fsm[];
    const uint32_t fsm_u32 = smem_u32(fsm);
    unsigned short* VH = fsm + FA_V0;
    unsigned short* VL = VH + 128 * VST;

    const int t = threadIdx.x;
    const int lane = t & 31;
    const int wid = t >> 5;
    const int g = lane >> 2;
    const int tg = lane & 3;
    const int bh = blockIdx.y;
    const int b = bh >> 4;
    const int h = bh & 15;
    const int q0 = ((int)gridDim.x - 1 - (int)blockIdx.x) * 64;
    const int qrow0 = q0 + wid * 16;

    const float* __restrict__ Qg = g_Q + ((size_t)bh * S_ + qrow0) * DH_;
    const unsigned short* __restrict__ KgH = g_KH + (size_t)bh * S_ * DH_;
    const unsigned short* __restrict__ KgL = g_KL + (size_t)bh * S_ * DH_;
    const unsigned short* __restrict__ VgH = g_VH + (size_t)bh * DH_ * S_;
    const unsigned short* __restrict__ VgL = g_VL + (size_t)bh * DH_ * S_;

    auto load_K_async = [&](int k0, int stg) {
        const uint32_t kb = fsm_u32 + (uint32_t)(stg * KSTAGE) * 2;
#pragma unroll
        for (int p = 0; p < 8; p++) {
            const int idx = t + p * 128;
            const int row = idx >> 4;
            const int sg = idx & 15;
            const size_t go = (size_t)(k0 + row) * DH_ + sg * 8;
            const uint32_t so = (uint32_t)(row * KST + sg * 8) * 2;
            CP_ASYNC16(kb + so, KgH + go);
            CP_ASYNC16(kb + (uint32_t)(64 * KST) * 2 + so, KgL + go);
        }
    };
    auto load_V_async = [&](int k0) {
        const uint32_t vb = fsm_u32 + (uint32_t)FA_V0 * 2;
#pragma unroll
        for (int p = 0; p < 8; p++) {
            const int idx = t + p * 128;
            const int row = idx >> 3;
            const int sg = idx & 7;
            const size_t go = (size_t)row * S_ + k0 + sg * 8;
            const uint32_t so = (uint32_t)(row * VST + sg * 8) * 2;
            CP_ASYNC16(vb + so, VgH + go);
            CP_ASYNC16(vb + (uint32_t)(128 * VST) * 2 + so, VgL + go);
        }
    };

    // Q fragments (hi/lo), register resident.
    uint32_t qh[8][4], ql[8][4];
#pragma unroll
    for (int ks = 0; ks < 8; ks++) {
        const int kc = ks * 16 + tg * 2;
        float2 v0 = *(const float2*)(Qg + (size_t)g * DH_ + kc);
        float2 v1 = *(const float2*)(Qg + (size_t)(g + 8) * DH_ + kc);
        float2 v2 = *(const float2*)(Qg + (size_t)g * DH_ + kc + 8);
        float2 v3 = *(const float2*)(Qg + (size_t)(g + 8) * DH_ + kc + 8);
        split2(v0.x, v0.y, qh[ks][0], ql[ks][0]);
        split2(v1.x, v1.y, qh[ks][1], ql[ks][1]);
        split2(v2.x, v2.y, qh[ks][2], ql[ks][2]);
        split2(v3.x, v3.y, qh[ks][3], ql[ks][3]);
    }

    float m0 = -1e30f, m1 = -1e30f, l0 = 0.f, l1 = 0.f;
    float o[16][4];
#pragma unroll
    for (int nt = 0; nt < 16; nt++)
#pragma unroll
        for (int c = 0; c < 4; c++) o[nt][c] = 0.f;

    const int nkt = (q0 >> 6) + 1;

    load_K_async(0, 0);   // prologue: K(0) -> stage 0
    CP_COMMIT();

    for (int kt = 0; kt < nkt; kt++) {
        const int st = kt & 1;
        const int k0 = kt * 64;
        const unsigned short* KHs = fsm + st * KSTAGE;
        const unsigned short* KLs = KHs + 64 * KST;

        __syncthreads();           // all done with previous V / K-stage reads
        load_V_async(k0);
        CP_COMMIT();
        if (kt + 1 < nkt) {
            load_K_async(k0 + 64, st ^ 1);
            CP_COMMIT();
            CP_WAIT(2);            // K(kt) complete; V + K(kt+1) pending
        } else {
            CP_WAIT(1);            // K(kt) complete; V pending
        }
        __syncthreads();

        // S = Q K^T (16 x 64 per warp), hi/lo compensated
        float sc[8][4];
#pragma unroll
        for (int nt = 0; nt < 8; nt++)
#pragma unroll
            for (int c = 0; c < 4; c++) sc[nt][c] = 0.f;

#pragma unroll
        for (int nt = 0; nt < 8; nt++) {
            const int r = nt * 8 + g;
#pragma unroll
            for (int ks = 0; ks < 8; ks++) {
                const int kc = ks * 16 + tg * 2;
                const unsigned short* pb = KHs + r * KST + kc;
                const uint32_t bh0 = *(const uint32_t*)(pb);
                const uint32_t bh1 = *(const uint32_t*)(pb + 8);
                const unsigned short* pl = KLs + r * KST + kc;
                const uint32_t bl0 = *(const uint32_t*)(pl);
                const uint32_t bl1 = *(const uint32_t*)(pl + 8);
                MMA16816(sc[nt], qh[ks], bh0, bh1);
                MMA16816(sc[nt], qh[ks], bl0, bl1);
                MMA16816(sc[nt], ql[ks], bh0, bh1);
            }
        }

        // Causal mask (diagonal tile only)
        if (kt == nkt - 1) {
            const int r0 = qrow0 + g, r1 = r0 + 8;
#pragma unroll
            for (int nt = 0; nt < 8; nt++) {
                const int c0 = k0 + nt * 8 + tg * 2;
                if (c0 > r0)     sc[nt][0] = -1e30f;
                if (c0 + 1 > r0) sc[nt][1] = -1e30f;
                if (c0 > r1)     sc[nt][2] = -1e30f;
                if (c0 + 1 > r1) sc[nt][3] = -1e30f;
            }
        }

        // Online softmax (4-lane reductions), overlaps in-flight V/K loads.
        float mx0 = -1e30f, mx1 = -1e30f;
#pragma unroll
        for (int nt = 0; nt < 8; nt++) {
            mx0 = fmaxf(mx0, fmaxf(sc[nt][0], sc[nt][1]));
            mx1 = fmaxf(mx1, fmaxf(sc[nt][2], sc[nt][3]));
        }
        mx0 = fmaxf(mx0, __shfl_xor_sync(0xffffffffu, mx0, 1));
        mx0 = fmaxf(mx0, __shfl_xor_sync(0xffffffffu, mx0, 2));
        mx1 = fmaxf(mx1, __shfl_xor_sync(0xffffffffu, mx1, 1));
        mx1 = fmaxf(mx1, __shfl_xor_sync(0xffffffffu, mx1, 2));
        const float nm0 = fmaxf(m0, mx0);
        const float nm1 = fmaxf(m1, mx1);
        const float al0 = __expf(m0 - nm0);
        const float al1 = __expf(m1 - nm1);
        m0 = nm0; m1 = nm1;

        float s0 = 0.f, s1 = 0.f;
        uint32_t pf[8][4];
#pragma unroll
        for (int nt = 0; nt < 8; nt++) {
            const float p0 = __expf(sc[nt][0] - nm0);
            const float p1 = __expf(sc[nt][1] - nm0);
            const float p2 = __expf(sc[nt][2] - nm1);
            const float p3 = __expf(sc[nt][3] - nm1);
            s0 += p0 + p1;
            s1 += p2 + p3;
            split2(p0, p1, pf[nt][0], pf[nt][1]);
            split2(p2, p3, pf[nt][2], pf[nt][3]);
        }
        s0 += __shfl_xor_sync(0xffffffffu, s0, 1);
        s0 += __shfl_xor_sync(0xffffffffu, s0, 2);
        s1 += __shfl_xor_sync(0xffffffffu, s1, 1);
        s1 += __shfl_xor_sync(0xffffffffu, s1, 2);
        l0 = l0 * al0 + s0;
        l1 = l1 * al1 + s1;
#pragma unroll
        for (int nt = 0; nt < 16; nt++) {
            o[nt][0] *= al0; o[nt][1] *= al0;
            o[nt][2] *= al1; o[nt][3] *= al1;
        }

        if (kt + 1 < nkt) { CP_WAIT(1); }   // V complete; K(kt+1) pending
        else              { CP_WAIT(0); }
        __syncthreads();

        // O += P V  (P fragments already in A layout)
#pragma unroll
        for (int kk = 0; kk < 4; kk++) {
            const uint32_t aH[4] = {pf[2 * kk][0], pf[2 * kk][2],
                                    pf[2 * kk + 1][0], pf[2 * kk + 1][2]};
            const uint32_t aL[4] = {pf[2 * kk][1], pf[2 * kk][3],
                                    pf[2 * kk + 1][1], pf[2 * kk + 1][3]};
            const int kc = kk * 16 + tg * 2;
#pragma unroll
            for (int nt = 0; nt < 16; nt++) {
                const int r = nt * 8 + g;
                const unsigned short* pb = VH + r * VST + kc;
                const uint32_t bh0 = *(const uint32_t*)(pb);
                const uint32_t bh1 = *(const uint32_t*)(pb + 8);
                const unsigned short* pl = VL + r * VST + kc;
                const uint32_t bl0 = *(const uint32_t*)(pl);
                const uint32_t bl1 = *(const uint32_t*)(pl + 8);
                MMA16816(o[nt], aH, bh0, bh1);
                MMA16816(o[nt], aH, bl0, bl1);
                MMA16816(o[nt], aL, bh0, bh1);
            }
        }
    }

    // Epilogue: normalize by l, softmax over head dim (128 cols), write.
    const float inv0 = 1.f / l0;
    const float inv1 = 1.f / l1;
#pragma unroll
    for (int nt = 0; nt < 16; nt++) {
        o[nt][0] *= inv0; o[nt][1] *= inv0;
        o[nt][2] *= inv1; o[nt][3] *= inv1;
    }
    float mxA = -1e30f, mxB = -1e30f;
#pragma unroll
    for (int nt = 0; nt < 16; nt++) {
        mxA = fmaxf(mxA, fmaxf(o[nt][0], o[nt][1]));
        mxB = fmaxf(mxB, fmaxf(o[nt][2], o[nt][3]));
    }
    mxA = fmaxf(mxA, __shfl_xor_sync(0xffffffffu, mxA, 1));
    mxA = fmaxf(mxA, __shfl_xor_sync(0xffffffffu, mxA, 2));
    mxB = fmaxf(mxB, __shfl_xor_sync(0xffffffffu, mxB, 1));
    mxB = fmaxf(mxB, __shfl_xor_sync(0xffffffffu, mxB, 2));
    float sA = 0.f, sB = 0.f;
#pragma unroll
    for (int nt = 0; nt < 16; nt++) {
        o[nt][0] = __expf(o[nt][0] - mxA);
        o[nt][1] = __expf(o[nt][1] - mxA);
        o[nt][2] = __expf(o[nt][2] - mxB);
        o[nt][3] = __expf(o[nt][3] - mxB);
        sA += o[nt][0] + o[nt][1];
        sB += o[nt][2] + o[nt][3];
    }
    sA += __shfl_xor_sync(0xffffffffu, sA, 1);
    sA += __shfl_xor_sync(0xffffffffu, sA, 2);
    sB += __shfl_xor_sync(0xffffffffu, sB, 1);
    sB += __shfl_xor_sync(0xffffffffu, sB, 2);
    const float iA = 1.f / sA;
    const float iB = 1.f / sB;

    const int r0 = qrow0 + g;
    const int r1 = r0 + 8;
    float* op0 = out + ((size_t)b * S_ + r0) * D_ + h * DH_;
    float* op1 = out + ((size_t)b * S_ + r1) * D_ + h * DH_;
#pragma unroll
    for (int nt = 0; nt < 16; nt++) {
        const int d = nt * 8 + tg * 2;
        float2 wA; wA.x = o[nt][0] * iA; wA.y = o[nt][1] * iA;
        float2 wB; wB.x = o[nt][2] * iB; wB.y = o[nt][3] * iB;
        *(float2*)(op0 + d) = wA;
        *(float2*)(op1 + d) = wB;
    }
}

// ---------------------------------------------------------------------------
extern "C" void kernel_launch(void* const* d_in, const int* in_sizes, int n_in,
                              void* d_out, int out_size)
{
    (void)in_sizes; (void)n_in; (void)out_size;
    const float* x  = (const float*)d_in[0];
    const float* wq = (const float*)d_in[1];
    const float* wk = (const float*)d_in[2];
    const float* wv = (const float*)d_in[3];
    const float* rc = (const float*)d_in[4];
    const float* rs = (const float*)d_in[5];
    float* out = (float*)d_out;

    cudaFuncSetAttribute(proj_mma_kernel,
                         cudaFuncAttributeMaxDynamicSharedMemorySize, PROJ_SMEM);
    cudaFuncSetAttribute(fa_mma_kernel,
                         cudaFuncAttributeMaxDynamicSharedMemorySize, FA_SMEM_B);

    dim3 sg(264, 4);
    presplit_kernel<<<sg, 256>>>(x, wq, wk, wv);

    dim3 pg(D_ / 256, (B_ * S_) / 128, 3);
    proj_mma_kernel<<<pg, 256, PROJ_SMEM>>>(rc, rs);

    dim3 fg(S_ / 64, B_ * H_);
    fa_mma_kernel<<<fg, 128, FA_SMEM_B>>>(out);
}